// round 6
// baseline (speedup 1.0000x reference)
#include <cuda_runtime.h>
#include <cstdint>

#define DIM   1024
#define SEQ   2048
#define BATCH 2
#define NH    16
#define HD    64
#define MROWS (BATCH*SEQ)   /* 4096 */

/* ---------------- scratch (device globals: allocation-free) -------------- */
__device__ uint32_t g_qt[MROWS*DIM];      /* tf32 bits of q,k,v inputs */
__device__ uint32_t g_kt[MROWS*DIM];
__device__ uint32_t g_vt[MROWS*DIM];
__device__ uint32_t g_wq[DIM*DIM];        /* tf32 bits of weights */
__device__ uint32_t g_wk[DIM*DIM];
__device__ uint32_t g_wv[DIM*DIM];
__device__ uint32_t g_wo[DIM*DIM];
__device__ uint32_t g_qh[BATCH*NH*SEQ*HD];  /* tf32 [B,H,S,hd], pre-scaled */
__device__ uint32_t g_kh[BATCH*NH*SEQ*HD];
__device__ uint32_t g_vh[BATCH*NH*SEQ*HD];
__device__ uint32_t g_ao[MROWS*DIM];        /* tf32 [B*S, D] attn output */

__device__ __forceinline__ uint32_t f32_tf32(float f) {
    uint32_t r;
    asm("cvt.rna.tf32.f32 %0, %1;" : "=r"(r) : "f"(f));
    return r;
}

__device__ __forceinline__ void mma_tf32(float* d, const uint32_t* a, const uint32_t* b) {
    asm volatile(
        "mma.sync.aligned.m16n8k8.row.col.f32.tf32.tf32.f32 "
        "{%0,%1,%2,%3}, {%4,%5,%6,%7}, {%8,%9}, {%0,%1,%2,%3};\n"
        : "+f"(d[0]), "+f"(d[1]), "+f"(d[2]), "+f"(d[3])
        : "r"(a[0]), "r"(a[1]), "r"(a[2]), "r"(a[3]), "r"(b[0]), "r"(b[1]));
}

__device__ __forceinline__ void cp16(uint32_t* smem_dst, const uint32_t* gsrc) {
    uint32_t sa = (uint32_t)__cvta_generic_to_shared(smem_dst);
    asm volatile("cp.async.cg.shared.global [%0], [%1], 16;"
                 :: "r"(sa), "l"(gsrc) : "memory");
}
#define CP_COMMIT() asm volatile("cp.async.commit_group;" ::: "memory")
#define CP_WAIT(n)  asm volatile("cp.async.wait_group %0;" :: "n"(n) : "memory")

/* ------------------- fused fp32 -> tf32 bits convert --------------------- */
__global__ __launch_bounds__(256) void cvt_all_kernel(
    const float* __restrict__ s0, const float* __restrict__ s1,
    const float* __restrict__ s2, const float* __restrict__ s3,
    const float* __restrict__ s4, const float* __restrict__ s5,
    const float* __restrict__ s6,
    uint32_t* __restrict__ d0, uint32_t* __restrict__ d1,
    uint32_t* __restrict__ d2, uint32_t* __restrict__ d3,
    uint32_t* __restrict__ d4, uint32_t* __restrict__ d5,
    uint32_t* __restrict__ d6)
{
    const float* srcs[7] = { s0, s1, s2, s3, s4, s5, s6 };
    uint32_t*    dsts[7] = { d0, d1, d2, d3, d4, d5, d6 };
    const int ns[7] = { MROWS*DIM/4, MROWS*DIM/4, MROWS*DIM/4,
                        DIM*DIM/4, DIM*DIM/4, DIM*DIM/4, DIM*DIM/4 };
    const int t = blockIdx.y;
    const int i = blockIdx.x * 256 + threadIdx.x;
    if (i < ns[t]) {
        float4 v = *(const float4*)(srcs[t] + (size_t)i * 4);
        *(uint4*)(dsts[t] + (size_t)i * 4) = make_uint4(
            f32_tf32(v.x), f32_tf32(v.y), f32_tf32(v.z), f32_tf32(v.w));
    }
}

/* =================== tf32 GEMM: C = A @ W^T =============================== */
/* block tile 128x256x32, 256 thr / 8 warps, warp tile 64x64, 4-stage async  */
#define BM 128
#define BN 256
#define BK 32
#define NKT (DIM / BK)
#define A_U32 (BM * BK)            /* 4096  */
#define B_U32 (BN * BK)            /* 8192  */
#define STG_U32 (A_U32 + B_U32)    /* 12288 */
#define NSTAGE 4
#define GEMM_SMEM (NSTAGE * STG_U32 * 4)  /* 196608 B */

__device__ __forceinline__ int swz(int row, int k) {
    return row * BK + (k ^ ((row & 7) << 2));
}

__device__ __forceinline__ void stage_async(
    uint32_t* __restrict__ As, uint32_t* __restrict__ Bs,
    const uint32_t* __restrict__ A, const uint32_t* __restrict__ W,
    int m0, int n0, int kc, int tid)
{
#pragma unroll
    for (int i = 0; i < 4; i++) {           /* A: 128 rows */
        int f = tid + (i << 8);
        int row = f >> 3, c4 = (f & 7) << 2;
        cp16(As + swz(row, c4), A + (size_t)(m0 + row) * DIM + kc + c4);
    }
#pragma unroll
    for (int i = 0; i < 8; i++) {           /* B: 256 rows */
        int f = tid + (i << 8);
        int row = f >> 3, c4 = (f & 7) << 2;
        cp16(Bs + swz(row, c4), W + (size_t)(n0 + row) * DIM + kc + c4);
    }
}

/* mode: 0 = fp32 flat output (final), 1 = tf32 head-split (qkv)            */
__device__ __forceinline__ void gemm_body(
    const uint32_t* __restrict__ A, const uint32_t* __restrict__ W,
    float* __restrict__ Cf, uint32_t* __restrict__ Ch, int mode, float scale)
{
    extern __shared__ uint32_t smg[];

    const int tid  = threadIdx.x;
    const int lane = tid & 31;
    const int wid  = tid >> 5;
    const int wm0  = (wid & 1) << 6;        /* 0 or 64          */
    const int wn0  = (wid >> 1) << 6;       /* 0,64,128,192     */
    const int m0   = blockIdx.y * BM;
    const int n0   = blockIdx.x * BN;
    const int r0   = lane >> 2;
    const int tig  = lane & 3;

    float acc[4][8][4];
#pragma unroll
    for (int mt = 0; mt < 4; mt++)
#pragma unroll
        for (int nt = 0; nt < 8; nt++)
#pragma unroll
            for (int e = 0; e < 4; e++) acc[mt][nt][e] = 0.f;

    /* prologue: fill stages 0..NSTAGE-2 */
#pragma unroll
    for (int p = 0; p < NSTAGE - 1; p++) {
        stage_async(smg + p * STG_U32, smg + p * STG_U32 + A_U32,
                    A, W, m0, n0, p * BK, tid);
        CP_COMMIT();
    }

    for (int kt = 0; kt < NKT; kt++) {
        CP_WAIT(NSTAGE - 2);               /* stage kt resident */
        __syncthreads();                   /* one barrier per k-tile */

        if (kt + NSTAGE - 1 < NKT) {
            const int w = (kt + NSTAGE - 1) % NSTAGE;
            stage_async(smg + w * STG_U32, smg + w * STG_U32 + A_U32,
                        A, W, m0, n0, (kt + NSTAGE - 1) * BK, tid);
        }
        CP_COMMIT();                       /* always commit to keep groups aligned */

        const uint32_t* __restrict__ Ab = smg + (kt % NSTAGE) * STG_U32;
        const uint32_t* __restrict__ Bb = Ab + A_U32;
#pragma unroll
        for (int ks = 0; ks < 4; ks++) {
            const int k = (ks << 3) + tig;
            uint32_t af[4][4], bf[8][2];
#pragma unroll
            for (int mt = 0; mt < 4; mt++) {
                int row = wm0 + (mt << 4) + r0;
                af[mt][0] = Ab[swz(row,     k)];
                af[mt][1] = Ab[swz(row + 8, k)];
                af[mt][2] = Ab[swz(row,     k + 4)];
                af[mt][3] = Ab[swz(row + 8, k + 4)];
            }
#pragma unroll
            for (int nt = 0; nt < 8; nt++) {
                int n = wn0 + (nt << 3) + r0;
                bf[nt][0] = Bb[swz(n, k)];
                bf[nt][1] = Bb[swz(n, k + 4)];
            }
#pragma unroll
            for (int mt = 0; mt < 4; mt++)
#pragma unroll
                for (int nt = 0; nt < 8; nt++)
                    mma_tf32(acc[mt][nt], af[mt], bf[nt]);
        }
    }

#pragma unroll
    for (int mt = 0; mt < 4; mt++) {
#pragma unroll
        for (int half = 0; half < 2; half++) {
            const int m = m0 + wm0 + (mt << 4) + r0 + (half << 3);
            if (mode == 1) {
                const int b = m >> 11, srow = m & (SEQ - 1);
#pragma unroll
                for (int nt = 0; nt < 8; nt++) {
                    int col = n0 + wn0 + (nt << 3) + (tig << 1);
                    int h = col >> 6, dd = col & 63;
                    uint2 val = make_uint2(
                        f32_tf32(acc[mt][nt][half * 2]     * scale),
                        f32_tf32(acc[mt][nt][half * 2 + 1] * scale));
                    *(uint2*)(Ch + ((size_t)((b * NH + h) * SEQ + srow) << 6) + dd) = val;
                }
            } else {
#pragma unroll
                for (int nt = 0; nt < 8; nt++) {
                    int col = n0 + wn0 + (nt << 3) + (tig << 1);
                    float2 val = make_float2(acc[mt][nt][half * 2],
                                             acc[mt][nt][half * 2 + 1]);
                    *(float2*)(Cf + (size_t)m * DIM + col) = val;
                }
            }
        }
    }
}

__global__ __launch_bounds__(256) void gemm_qkv(
    const uint32_t* __restrict__ qt, const uint32_t* __restrict__ kt_,
    const uint32_t* __restrict__ vt, const uint32_t* __restrict__ wq,
    const uint32_t* __restrict__ wk, const uint32_t* __restrict__ wv,
    uint32_t* __restrict__ qh, uint32_t* __restrict__ kh, uint32_t* __restrict__ vh)
{
    const uint32_t* A; const uint32_t* W; uint32_t* C; float scale;
    if (blockIdx.z == 0)      { A = qt;  W = wq; C = qh; scale = 0.125f; }
    else if (blockIdx.z == 1) { A = kt_; W = wk; C = kh; scale = 1.0f;   }
    else                      { A = vt;  W = wv; C = vh; scale = 1.0f;   }
    gemm_body(A, W, nullptr, C, 1, scale);
}

__global__ __launch_bounds__(256) void gemm_out(
    const uint32_t* __restrict__ A, const uint32_t* __restrict__ W,
    float* __restrict__ C)
{
    gemm_body(A, W, C, nullptr, 0, 1.0f);
}

/* ============ tensor-core flash attention (causal), tf32 mma ============== */
#define SW64(row, k) ((row) * 64 + ((k) ^ (((row) & 7) << 3)))

__global__ __launch_bounds__(128) void flash_attn(
    const uint32_t* __restrict__ Qh, const uint32_t* __restrict__ Kh,
    const uint32_t* __restrict__ Vh, uint32_t* __restrict__ AO)
{
    extern __shared__ uint32_t fsm[];
    uint32_t* Qs = fsm;                  /* 128x64 tf32, swizzled */
    uint32_t* Ks = fsm + 8192;           /* 64x64  [key][hd]      */
    uint32_t* Vt = fsm + 12288;          /* 64x64  [hd][key]      */
    uint32_t* Ps = fsm + 16384;          /* 128x64 P              */

    const int bh = blockIdx.y;
    const int qt = gridDim.x - 1 - blockIdx.x;   /* heavy tiles first */
    const int q0 = qt * 128;
    const uint32_t* Qb = Qh + (size_t)bh * SEQ * HD;
    const uint32_t* Kb = Kh + (size_t)bh * SEQ * HD;
    const uint32_t* Vb = Vh + (size_t)bh * SEQ * HD;

    const int tid  = threadIdx.x;
    const int lane = tid & 31;
    const int wid  = tid >> 5;
    const int r0   = lane >> 2;
    const int tig  = lane & 3;
    const int wq   = wid << 5;

    /* async-load Q tile (already tf32 + pre-scaled) */
#pragma unroll
    for (int i = 0; i < 16; i++) {
        int f = tid + (i << 7);
        int row = f >> 4, c4 = (f & 15) << 2;
        cp16(Qs + SW64(row, c4), Qb + (size_t)(q0 + row) * HD + c4);
    }
    CP_COMMIT();

    float o[2][8][4];
    float mi[4], li[4];
#pragma unroll
    for (int i = 0; i < 4; i++) { mi[i] = -1e30f; li[i] = 0.f; }
#pragma unroll
    for (int mt = 0; mt < 2; mt++)
#pragma unroll
        for (int nt = 0; nt < 8; nt++)
#pragma unroll
            for (int e = 0; e < 4; e++) o[mt][nt][e] = 0.f;

    const int nkt = 2 * qt + 2;
    for (int kt = 0; kt < nkt; kt++) {
        const int k0 = kt << 6;
        const uint32_t* Kp = Kb + (size_t)k0 * HD;
#pragma unroll
        for (int i = 0; i < 8; i++) {
            int f = tid + (i << 7);
            int row = f >> 4, c4 = (f & 15) << 2;
            cp16(Ks + SW64(row, c4), Kp + (size_t)row * HD + c4);
        }
        CP_COMMIT();
        /* V tile transposed: raw bit scatter (conflict-free) */
        const uint32_t* Vp = Vb + (size_t)k0 * HD;
#pragma unroll
        for (int i = 0; i < 8; i++) {
            int f = tid + (i << 7);
            int key = f & 63, c4 = (f >> 6) << 2;
            uint4 vv = *(const uint4*)(Vp + (size_t)key * HD + c4);
            Vt[SW64(c4 + 0, key)] = vv.x;
            Vt[SW64(c4 + 1, key)] = vv.y;
            Vt[SW64(c4 + 2, key)] = vv.z;
            Vt[SW64(c4 + 3, key)] = vv.w;
        }
        CP_WAIT(0);
        __syncthreads();

        const bool active = (k0 <= q0 + wq + 31);
        if (active) {
            float s[2][8][4];
#pragma unroll
            for (int mt = 0; mt < 2; mt++)
#pragma unroll
                for (int nt = 0; nt < 8; nt++)
#pragma unroll
                    for (int e = 0; e < 4; e++) s[mt][nt][e] = 0.f;

#pragma unroll
            for (int ks = 0; ks < 8; ks++) {
                const int k = (ks << 3) + tig;
                uint32_t af[2][4], bf[8][2];
#pragma unroll
                for (int mt = 0; mt < 2; mt++) {
                    int row = wq + (mt << 4) + r0;
                    af[mt][0] = Qs[SW64(row,     k)];
                    af[mt][1] = Qs[SW64(row + 8, k)];
                    af[mt][2] = Qs[SW64(row,     k + 4)];
                    af[mt][3] = Qs[SW64(row + 8, k + 4)];
                }
#pragma unroll
                for (int nt = 0; nt < 8; nt++) {
                    int n = (nt << 3) + r0;
                    bf[nt][0] = Ks[SW64(n, k)];
                    bf[nt][1] = Ks[SW64(n, k + 4)];
                }
#pragma unroll
                for (int mt = 0; mt < 2; mt++)
#pragma unroll
                    for (int nt = 0; nt < 8; nt++)
                        mma_tf32(s[mt][nt], af[mt], bf[nt]);
            }

            if (k0 + 63 > q0 + wq) {
#pragma unroll
                for (int mt = 0; mt < 2; mt++)
#pragma unroll
                    for (int nt = 0; nt < 8; nt++)
#pragma unroll
                        for (int e = 0; e < 4; e++) {
                            int rg = q0 + wq + (mt << 4) + ((e >> 1) << 3) + r0;
                            int cg = k0 + (nt << 3) + (tig << 1) + (e & 1);
                            if (cg > rg) s[mt][nt][e] = -1e30f;
                        }
            }

#pragma unroll
            for (int mt = 0; mt < 2; mt++) {
#pragma unroll
                for (int half = 0; half < 2; half++) {
                    const int ri = mt * 2 + half;
                    float mx = -1e30f;
#pragma unroll
                    for (int nt = 0; nt < 8; nt++)
                        mx = fmaxf(mx, fmaxf(s[mt][nt][half*2], s[mt][nt][half*2+1]));
                    mx = fmaxf(mx, __shfl_xor_sync(0xffffffffu, mx, 1));
                    mx = fmaxf(mx, __shfl_xor_sync(0xffffffffu, mx, 2));
                    float mnew = fmaxf(mi[ri], mx);
                    float corr = __expf(mi[ri] - mnew);
                    float sum = 0.f;
                    const int prow = wq + (mt << 4) + (half << 3) + r0;
#pragma unroll
                    for (int nt = 0; nt < 8; nt++) {
                        float p0 = __expf(s[mt][nt][half*2]     - mnew);
                        float p1 = __expf(s[mt][nt][half*2 + 1] - mnew);
                        sum += p0 + p1;
                        *(uint2*)(Ps + SW64(prow, (nt << 3) + (tig << 1))) =
                            make_uint2(f32_tf32(p0), f32_tf32(p1));
                    }
                    sum += __shfl_xor_sync(0xffffffffu, sum, 1);
                    sum += __shfl_xor_sync(0xffffffffu, sum, 2);
                    li[ri] = li[ri] * corr + sum;
                    mi[ri] = mnew;
#pragma unroll
                    for (int nt = 0; nt < 8; nt++) {
                        o[mt][nt][half*2]     *= corr;
                        o[mt][nt][half*2 + 1] *= corr;
                    }
                }
            }
            __syncwarp();

#pragma unroll
            for (int ks = 0; ks < 8; ks++) {
                const int k = (ks << 3) + tig;
                uint32_t af[2][4], bf[8][2];
#pragma unroll
                for (int mt = 0; mt < 2; mt++) {
                    int row = wq + (mt << 4) + r0;
                    af[mt][0] = Ps[SW64(row,     k)];
                    af[mt][1] = Ps[SW64(row + 8, k)];
                    af[mt][2] = Ps[SW64(row,     k + 4)];
                    af[mt][3] = Ps[SW64(row + 8, k + 4)];
                }
#pragma unroll
                for (int nt = 0; nt < 8; nt++) {
                    int n = (nt << 3) + r0;
                    bf[nt][0] = Vt[SW64(n, k)];
                    bf[nt][1] = Vt[SW64(n, k + 4)];
                }
#pragma unroll
                for (int mt = 0; mt < 2; mt++)
#pragma unroll
                    for (int nt = 0; nt < 8; nt++)
                        mma_tf32(o[mt][nt], af[mt], bf[nt]);
            }
        }
        __syncthreads();
    }

    /* epilogue: normalize, store tf32 bits into AO */
    const int b = bh >> 4, h = bh & 15;
#pragma unroll
    for (int mt = 0; mt < 2; mt++) {
#pragma unroll
        for (int half = 0; half < 2; half++) {
            const float inv = 1.f / li[mt * 2 + half];
            const int rg = q0 + wq + (mt << 4) + (half << 3) + r0;
            uint32_t* row = AO + (size_t)(b * SEQ + rg) * DIM + (h << 6);
#pragma unroll
            for (int nt = 0; nt < 8; nt++) {
                *(uint2*)(row + (nt << 3) + (tig << 1)) = make_uint2(
                    f32_tf32(o[mt][nt][half*2] * inv),
                    f32_tf32(o[mt][nt][half*2 + 1] * inv));
            }
        }
    }
}

/* ---------------- launch -------------------------------------------------- */
extern "C" void kernel_launch(void* const* d_in, const int* in_sizes, int n_in,
                              void* d_out, int out_size)
{
    const float* q  = (const float*)d_in[0];
    const float* k  = (const float*)d_in[1];
    const float* v  = (const float*)d_in[2];
    const float* wq = (const float*)d_in[3];
    const float* wk = (const float*)d_in[4];
    const float* wv = (const float*)d_in[5];
    const float* wo = (const float*)d_in[6];

    uint32_t *qt, *kt, *vt, *wqt, *wkt, *wvt, *wot, *qh, *kh, *vh, *ao;
    cudaGetSymbolAddress((void**)&qt,  g_qt);
    cudaGetSymbolAddress((void**)&kt,  g_kt);
    cudaGetSymbolAddress((void**)&vt,  g_vt);
    cudaGetSymbolAddress((void**)&wqt, g_wq);
    cudaGetSymbolAddress((void**)&wkt, g_wk);
    cudaGetSymbolAddress((void**)&wvt, g_wv);
    cudaGetSymbolAddress((void**)&wot, g_wo);
    cudaGetSymbolAddress((void**)&qh,  g_qh);
    cudaGetSymbolAddress((void**)&kh,  g_kh);
    cudaGetSymbolAddress((void**)&vh,  g_vh);
    cudaGetSymbolAddress((void**)&ao,  g_ao);

    const int flash_smem = (8192 + 4096 + 4096 + 8192) * 4;  /* 98304 */
    cudaFuncSetAttribute(gemm_qkv,  cudaFuncAttributeMaxDynamicSharedMemorySize, GEMM_SMEM);
    cudaFuncSetAttribute(gemm_out,  cudaFuncAttributeMaxDynamicSharedMemorySize, GEMM_SMEM);
    cudaFuncSetAttribute(flash_attn, cudaFuncAttributeMaxDynamicSharedMemorySize, flash_smem);

    /* fused fp32 -> tf32 pre-conversion */
    dim3 gcvt(MROWS * DIM / 4 / 256, 7);     /* 4096 x 7 */
    cvt_all_kernel<<<gcvt, 256>>>(q, k, v, wq, wk, wv, wo,
                                  qt, kt, vt, wqt, wkt, wvt, wot);

    dim3 gqkv(DIM / BN, MROWS / BM, 3);        /* 4 x 32 x 3 */
    gemm_qkv<<<gqkv, 256, GEMM_SMEM>>>(qt, kt, vt, wqt, wkt, wvt, qh, kh, vh);

    flash_attn<<<dim3(SEQ / 128, BATCH * NH), 128, flash_smem>>>(qh, kh, vh, ao);

    dim3 gout(DIM / BN, MROWS / BM);           /* 4 x 32 */
    gemm_out<<<gout, 256, GEMM_SMEM>>>(ao, wot, (float*)d_out);
}

// round 7
// speedup vs baseline: 1.0830x; 1.0830x over previous
#include <cuda_runtime.h>
#include <cstdint>

#define DIM   1024
#define SEQ   2048
#define BATCH 2
#define NH    16
#define HD    64
#define MROWS (BATCH*SEQ)   /* 4096 */

/* ---------------- scratch (device globals: allocation-free) -------------- */
__device__ uint32_t g_qt[MROWS*DIM];      /* tf32 bits of q,k,v inputs */
__device__ uint32_t g_kt[MROWS*DIM];
__device__ uint32_t g_vt[MROWS*DIM];
__device__ uint32_t g_wq[DIM*DIM];        /* tf32 bits of weights */
__device__ uint32_t g_wk[DIM*DIM];
__device__ uint32_t g_wv[DIM*DIM];
__device__ uint32_t g_wo[DIM*DIM];
__device__ uint32_t g_qh[BATCH*NH*SEQ*HD];  /* tf32 [B,H,S,hd], pre-scaled */
__device__ uint32_t g_kh[BATCH*NH*SEQ*HD];
__device__ uint32_t g_vh[BATCH*NH*SEQ*HD];
__device__ uint32_t g_ao[MROWS*DIM];        /* tf32 [B*S, D] attn output */

__device__ __forceinline__ uint32_t f32_tf32(float f) {
    uint32_t r;
    asm("cvt.rna.tf32.f32 %0, %1;" : "=r"(r) : "f"(f));
    return r;
}

__device__ __forceinline__ void mma_tf32(float* d, const uint32_t* a, const uint32_t* b) {
    asm volatile(
        "mma.sync.aligned.m16n8k8.row.col.f32.tf32.tf32.f32 "
        "{%0,%1,%2,%3}, {%4,%5,%6,%7}, {%8,%9}, {%0,%1,%2,%3};\n"
        : "+f"(d[0]), "+f"(d[1]), "+f"(d[2]), "+f"(d[3])
        : "r"(a[0]), "r"(a[1]), "r"(a[2]), "r"(a[3]), "r"(b[0]), "r"(b[1]));
}

__device__ __forceinline__ void cp16(uint32_t* smem_dst, const uint32_t* gsrc) {
    uint32_t sa = (uint32_t)__cvta_generic_to_shared(smem_dst);
    asm volatile("cp.async.cg.shared.global [%0], [%1], 16;"
                 :: "r"(sa), "l"(gsrc) : "memory");
}
#define CP_COMMIT() asm volatile("cp.async.commit_group;" ::: "memory")
#define CP_WAIT(n)  asm volatile("cp.async.wait_group %0;" :: "n"(n) : "memory")

/* ------------------- fused fp32 -> tf32 bits convert --------------------- */
__global__ __launch_bounds__(256) void cvt_all_kernel(
    const float* __restrict__ s0, const float* __restrict__ s1,
    const float* __restrict__ s2, const float* __restrict__ s3,
    const float* __restrict__ s4, const float* __restrict__ s5,
    const float* __restrict__ s6,
    uint32_t* __restrict__ d0, uint32_t* __restrict__ d1,
    uint32_t* __restrict__ d2, uint32_t* __restrict__ d3,
    uint32_t* __restrict__ d4, uint32_t* __restrict__ d5,
    uint32_t* __restrict__ d6)
{
    const float* srcs[7] = { s0, s1, s2, s3, s4, s5, s6 };
    uint32_t*    dsts[7] = { d0, d1, d2, d3, d4, d5, d6 };
    const int ns[7] = { MROWS*DIM/4, MROWS*DIM/4, MROWS*DIM/4,
                        DIM*DIM/4, DIM*DIM/4, DIM*DIM/4, DIM*DIM/4 };
    const int t = blockIdx.y;
    const int i = blockIdx.x * 256 + threadIdx.x;
    if (i < ns[t]) {
        float4 v = *(const float4*)(srcs[t] + (size_t)i * 4);
        *(uint4*)(dsts[t] + (size_t)i * 4) = make_uint4(
            f32_tf32(v.x), f32_tf32(v.y), f32_tf32(v.z), f32_tf32(v.w));
    }
}

/* =================== tf32 GEMM: C = A @ W^T =============================== */
/* block tile 128x256x32, 256 thr / 8 warps, warp tile 64x64, 4-stage async  */
#define BM 128
#define BN 256
#define BK 32
#define NKT (DIM / BK)
#define A_U32 (BM * BK)            /* 4096  */
#define B_U32 (BN * BK)            /* 8192  */
#define STG_U32 (A_U32 + B_U32)    /* 12288 */
#define NSTAGE 4
#define GEMM_SMEM (NSTAGE * STG_U32 * 4)  /* 196608 B */

__device__ __forceinline__ int swz(int row, int k) {
    return row * BK + (k ^ ((row & 7) << 2));
}

__device__ __forceinline__ void stage_async(
    uint32_t* __restrict__ As, uint32_t* __restrict__ Bs,
    const uint32_t* __restrict__ A, const uint32_t* __restrict__ W,
    int m0, int n0, int kc, int tid)
{
#pragma unroll
    for (int i = 0; i < 4; i++) {           /* A: 128 rows */
        int f = tid + (i << 8);
        int row = f >> 3, c4 = (f & 7) << 2;
        cp16(As + swz(row, c4), A + (size_t)(m0 + row) * DIM + kc + c4);
    }
#pragma unroll
    for (int i = 0; i < 8; i++) {           /* B: 256 rows */
        int f = tid + (i << 8);
        int row = f >> 3, c4 = (f & 7) << 2;
        cp16(Bs + swz(row, c4), W + (size_t)(n0 + row) * DIM + kc + c4);
    }
}

/* mode: 0 = fp32 flat output (final), 1 = tf32 head-split (qkv)            */
__device__ __forceinline__ void gemm_body(
    const uint32_t* __restrict__ A, const uint32_t* __restrict__ W,
    float* __restrict__ Cf, uint32_t* __restrict__ Ch, int mode, float scale)
{
    extern __shared__ uint32_t smg[];

    const int tid  = threadIdx.x;
    const int lane = tid & 31;
    const int wid  = tid >> 5;
    const int wm0  = (wid & 1) << 6;        /* 0 or 64          */
    const int wn0  = (wid >> 1) << 6;       /* 0,64,128,192     */
    const int m0   = blockIdx.y * BM;
    const int n0   = blockIdx.x * BN;
    const int r0   = lane >> 2;
    const int tig  = lane & 3;

    float acc[4][8][4];
#pragma unroll
    for (int mt = 0; mt < 4; mt++)
#pragma unroll
        for (int nt = 0; nt < 8; nt++)
#pragma unroll
            for (int e = 0; e < 4; e++) acc[mt][nt][e] = 0.f;

#pragma unroll
    for (int p = 0; p < NSTAGE - 1; p++) {
        stage_async(smg + p * STG_U32, smg + p * STG_U32 + A_U32,
                    A, W, m0, n0, p * BK, tid);
        CP_COMMIT();
    }

    for (int kt = 0; kt < NKT; kt++) {
        CP_WAIT(NSTAGE - 2);
        __syncthreads();

        if (kt + NSTAGE - 1 < NKT) {
            const int w = (kt + NSTAGE - 1) % NSTAGE;
            stage_async(smg + w * STG_U32, smg + w * STG_U32 + A_U32,
                        A, W, m0, n0, (kt + NSTAGE - 1) * BK, tid);
        }
        CP_COMMIT();

        const uint32_t* __restrict__ Ab = smg + (kt % NSTAGE) * STG_U32;
        const uint32_t* __restrict__ Bb = Ab + A_U32;
#pragma unroll
        for (int ks = 0; ks < 4; ks++) {
            const int k = (ks << 3) + tig;
            uint32_t af[4][4], bf[8][2];
#pragma unroll
            for (int mt = 0; mt < 4; mt++) {
                int row = wm0 + (mt << 4) + r0;
                af[mt][0] = Ab[swz(row,     k)];
                af[mt][1] = Ab[swz(row + 8, k)];
                af[mt][2] = Ab[swz(row,     k + 4)];
                af[mt][3] = Ab[swz(row + 8, k + 4)];
            }
#pragma unroll
            for (int nt = 0; nt < 8; nt++) {
                int n = wn0 + (nt << 3) + r0;
                bf[nt][0] = Bb[swz(n, k)];
                bf[nt][1] = Bb[swz(n, k + 4)];
            }
#pragma unroll
            for (int mt = 0; mt < 4; mt++)
#pragma unroll
                for (int nt = 0; nt < 8; nt++)
                    mma_tf32(acc[mt][nt], af[mt], bf[nt]);
        }
    }

#pragma unroll
    for (int mt = 0; mt < 4; mt++) {
#pragma unroll
        for (int half = 0; half < 2; half++) {
            const int m = m0 + wm0 + (mt << 4) + r0 + (half << 3);
            if (mode == 1) {
                const int b = m >> 11, srow = m & (SEQ - 1);
#pragma unroll
                for (int nt = 0; nt < 8; nt++) {
                    int col = n0 + wn0 + (nt << 3) + (tig << 1);
                    int h = col >> 6, dd = col & 63;
                    uint2 val = make_uint2(
                        f32_tf32(acc[mt][nt][half * 2]     * scale),
                        f32_tf32(acc[mt][nt][half * 2 + 1] * scale));
                    *(uint2*)(Ch + ((size_t)((b * NH + h) * SEQ + srow) << 6) + dd) = val;
                }
            } else {
#pragma unroll
                for (int nt = 0; nt < 8; nt++) {
                    int col = n0 + wn0 + (nt << 3) + (tig << 1);
                    float2 val = make_float2(acc[mt][nt][half * 2],
                                             acc[mt][nt][half * 2 + 1]);
                    *(float2*)(Cf + (size_t)m * DIM + col) = val;
                }
            }
        }
    }
}

__global__ __launch_bounds__(256) void gemm_qkv(
    const uint32_t* __restrict__ qt, const uint32_t* __restrict__ kt_,
    const uint32_t* __restrict__ vt, const uint32_t* __restrict__ wq,
    const uint32_t* __restrict__ wk, const uint32_t* __restrict__ wv,
    uint32_t* __restrict__ qh, uint32_t* __restrict__ kh, uint32_t* __restrict__ vh)
{
    const uint32_t* A; const uint32_t* W; uint32_t* C; float scale;
    if (blockIdx.z == 0)      { A = qt;  W = wq; C = qh; scale = 0.125f; }
    else if (blockIdx.z == 1) { A = kt_; W = wk; C = kh; scale = 1.0f;   }
    else                      { A = vt;  W = wv; C = vh; scale = 1.0f;   }
    gemm_body(A, W, nullptr, C, 1, scale);
}

__global__ __launch_bounds__(256) void gemm_out(
    const uint32_t* __restrict__ A, const uint32_t* __restrict__ W,
    float* __restrict__ C)
{
    gemm_body(A, W, C, nullptr, 0, 1.0f);
}

/* ============ tensor-core flash attention (causal), tf32 mma ==============
   Pipelined: K double-buffered, V single-buffered in [key][hd] layout.
   SMEM: Q 32K | K0 16K | K1 16K | V 16K | P 32K = 112 KB -> 2 CTA/SM.      */
#define SW64(row, k) ((row) * 64 + ((k) ^ (((row) & 7) << 3)))

__global__ __launch_bounds__(128) void flash_attn(
    const uint32_t* __restrict__ Qh, const uint32_t* __restrict__ Kh,
    const uint32_t* __restrict__ Vh, uint32_t* __restrict__ AO)
{
    extern __shared__ uint32_t fsm[];
    uint32_t* Qs    = fsm;             /* 128x64 */
    uint32_t* Ksb[2];
    Ksb[0]          = fsm + 8192;      /* 64x64  */
    Ksb[1]          = fsm + 12288;     /* 64x64  */
    uint32_t* Vs    = fsm + 16384;     /* 64x64 [key][hd] */
    uint32_t* Ps    = fsm + 20480;     /* 128x64 */

    const int bh = blockIdx.y;
    const int qt = gridDim.x - 1 - blockIdx.x;   /* heavy tiles first */
    const int q0 = qt * 128;
    const uint32_t* Qb = Qh + (size_t)bh * SEQ * HD;
    const uint32_t* Kb = Kh + (size_t)bh * SEQ * HD;
    const uint32_t* Vb = Vh + (size_t)bh * SEQ * HD;

    const int tid  = threadIdx.x;
    const int lane = tid & 31;
    const int wid  = tid >> 5;
    const int r0   = lane >> 2;
    const int tig  = lane & 3;
    const int wq   = wid << 5;

    /* group 0: Q tile */
#pragma unroll
    for (int i = 0; i < 16; i++) {
        int f = tid + (i << 7);
        int row = f >> 4, c4 = (f & 15) << 2;
        cp16(Qs + SW64(row, c4), Qb + (size_t)(q0 + row) * HD + c4);
    }
    CP_COMMIT();
    /* group 1: K[0] */
#pragma unroll
    for (int i = 0; i < 8; i++) {
        int f = tid + (i << 7);
        int row = f >> 4, c4 = (f & 15) << 2;
        cp16(Ksb[0] + SW64(row, c4), Kb + (size_t)row * HD + c4);
    }
    CP_COMMIT();

    float o[2][8][4];
    float mi[4], li[4];
#pragma unroll
    for (int i = 0; i < 4; i++) { mi[i] = -1e30f; li[i] = 0.f; }
#pragma unroll
    for (int mt = 0; mt < 2; mt++)
#pragma unroll
        for (int nt = 0; nt < 8; nt++)
#pragma unroll
            for (int e = 0; e < 4; e++) o[mt][nt][e] = 0.f;

    const int nkt = 2 * qt + 2;
    for (int kt = 0; kt < nkt; kt++) {
        const int k0 = kt << 6;

        /* issue V[kt] (buffer free: PV(kt-1) done at prior end-sync) */
        const uint32_t* Vp = Vb + (size_t)k0 * HD;
#pragma unroll
        for (int i = 0; i < 8; i++) {
            int f = tid + (i << 7);
            int row = f >> 4, c4 = (f & 15) << 2;
            cp16(Vs + SW64(row, c4), Vp + (size_t)row * HD + c4);
        }
        CP_COMMIT();

        /* issue K[kt+1] prefetch */
        if (kt + 1 < nkt) {
            const uint32_t* Kp = Kb + (size_t)(k0 + 64) * HD;
            uint32_t* Kd = Ksb[(kt + 1) & 1];
#pragma unroll
            for (int i = 0; i < 8; i++) {
                int f = tid + (i << 7);
                int row = f >> 4, c4 = (f & 15) << 2;
                cp16(Kd + SW64(row, c4), Kp + (size_t)row * HD + c4);
            }
        }
        CP_COMMIT();

        /* wait K[kt] (pending allowed: V[kt], K[kt+1]) */
        CP_WAIT(2);
        __syncthreads();

        const uint32_t* Ks = Ksb[kt & 1];
        const bool active = (k0 <= q0 + wq + 31);
        if (active) {
            float s[2][8][4];
#pragma unroll
            for (int mt = 0; mt < 2; mt++)
#pragma unroll
                for (int nt = 0; nt < 8; nt++)
#pragma unroll
                    for (int e = 0; e < 4; e++) s[mt][nt][e] = 0.f;

#pragma unroll
            for (int ks = 0; ks < 8; ks++) {
                const int k = (ks << 3) + tig;
                uint32_t af[2][4], bf[8][2];
#pragma unroll
                for (int mt = 0; mt < 2; mt++) {
                    int row = wq + (mt << 4) + r0;
                    af[mt][0] = Qs[SW64(row,     k)];
                    af[mt][1] = Qs[SW64(row + 8, k)];
                    af[mt][2] = Qs[SW64(row,     k + 4)];
                    af[mt][3] = Qs[SW64(row + 8, k + 4)];
                }
#pragma unroll
                for (int nt = 0; nt < 8; nt++) {
                    int n = (nt << 3) + r0;
                    bf[nt][0] = Ks[SW64(n, k)];
                    bf[nt][1] = Ks[SW64(n, k + 4)];
                }
#pragma unroll
                for (int mt = 0; mt < 2; mt++)
#pragma unroll
                    for (int nt = 0; nt < 8; nt++)
                        mma_tf32(s[mt][nt], af[mt], bf[nt]);
            }

            if (k0 + 63 > q0 + wq) {
#pragma unroll
                for (int mt = 0; mt < 2; mt++)
#pragma unroll
                    for (int nt = 0; nt < 8; nt++)
#pragma unroll
                        for (int e = 0; e < 4; e++) {
                            int rg = q0 + wq + (mt << 4) + ((e >> 1) << 3) + r0;
                            int cg = k0 + (nt << 3) + (tig << 1) + (e & 1);
                            if (cg > rg) s[mt][nt][e] = -1e30f;
                        }
            }

#pragma unroll
            for (int mt = 0; mt < 2; mt++) {
#pragma unroll
                for (int half = 0; half < 2; half++) {
                    const int ri = mt * 2 + half;
                    float mx = -1e30f;
#pragma unroll
                    for (int nt = 0; nt < 8; nt++)
                        mx = fmaxf(mx, fmaxf(s[mt][nt][half*2], s[mt][nt][half*2+1]));
                    mx = fmaxf(mx, __shfl_xor_sync(0xffffffffu, mx, 1));
                    mx = fmaxf(mx, __shfl_xor_sync(0xffffffffu, mx, 2));
                    float mnew = fmaxf(mi[ri], mx);
                    float corr = __expf(mi[ri] - mnew);
                    float sum = 0.f;
                    const int prow = wq + (mt << 4) + (half << 3) + r0;
#pragma unroll
                    for (int nt = 0; nt < 8; nt++) {
                        float p0 = __expf(s[mt][nt][half*2]     - mnew);
                        float p1 = __expf(s[mt][nt][half*2 + 1] - mnew);
                        sum += p0 + p1;
                        *(uint2*)(Ps + SW64(prow, (nt << 3) + (tig << 1))) =
                            make_uint2(f32_tf32(p0), f32_tf32(p1));
                    }
                    sum += __shfl_xor_sync(0xffffffffu, sum, 1);
                    sum += __shfl_xor_sync(0xffffffffu, sum, 2);
                    li[ri] = li[ri] * corr + sum;
                    mi[ri] = mnew;
#pragma unroll
                    for (int nt = 0; nt < 8; nt++) {
                        o[mt][nt][half*2]     *= corr;
                        o[mt][nt][half*2 + 1] *= corr;
                    }
                }
            }
        }

        /* wait V[kt] (pending allowed: K[kt+1]) */
        CP_WAIT(1);
        __syncthreads();

        if (active) {
            /* O += P V ; B-fragment from Vs[key][hd]: b(n,k) = Vs[k][n] */
#pragma unroll
            for (int ks = 0; ks < 8; ks++) {
                const int k = (ks << 3) + tig;
                uint32_t af[2][4], bf[8][2];
#pragma unroll
                for (int mt = 0; mt < 2; mt++) {
                    int row = wq + (mt << 4) + r0;
                    af[mt][0] = Ps[SW64(row,     k)];
                    af[mt][1] = Ps[SW64(row + 8, k)];
                    af[mt][2] = Ps[SW64(row,     k + 4)];
                    af[mt][3] = Ps[SW64(row + 8, k + 4)];
                }
#pragma unroll
                for (int nt = 0; nt < 8; nt++) {
                    int n = (nt << 3) + r0;
                    bf[nt][0] = Vs[SW64(k,     n)];
                    bf[nt][1] = Vs[SW64(k + 4, n)];
                }
#pragma unroll
                for (int mt = 0; mt < 2; mt++)
#pragma unroll
                    for (int nt = 0; nt < 8; nt++)
                        mma_tf32(o[mt][nt], af[mt], bf[nt]);
            }
        }
        __syncthreads();   /* protect Vs reuse next iteration */
    }

    /* epilogue: normalize, store tf32 bits into AO */
    const int b = bh >> 4, h = bh & 15;
#pragma unroll
    for (int mt = 0; mt < 2; mt++) {
#pragma unroll
        for (int half = 0; half < 2; half++) {
            const float inv = 1.f / li[mt * 2 + half];
            const int rg = q0 + wq + (mt << 4) + (half << 3) + r0;
            uint32_t* row = AO + (size_t)(b * SEQ + rg) * DIM + (h << 6);
#pragma unroll
            for (int nt = 0; nt < 8; nt++) {
                *(uint2*)(row + (nt << 3) + (tig << 1)) = make_uint2(
                    f32_tf32(o[mt][nt][half*2] * inv),
                    f32_tf32(o[mt][nt][half*2 + 1] * inv));
            }
        }
    }
}

/* ---------------- launch -------------------------------------------------- */
extern "C" void kernel_launch(void* const* d_in, const int* in_sizes, int n_in,
                              void* d_out, int out_size)
{
    const float* q  = (const float*)d_in[0];
    const float* k  = (const float*)d_in[1];
    const float* v  = (const float*)d_in[2];
    const float* wq = (const float*)d_in[3];
    const float* wk = (const float*)d_in[4];
    const float* wv = (const float*)d_in[5];
    const float* wo = (const float*)d_in[6];

    uint32_t *qt, *kt, *vt, *wqt, *wkt, *wvt, *wot, *qh, *kh, *vh, *ao;
    cudaGetSymbolAddress((void**)&qt,  g_qt);
    cudaGetSymbolAddress((void**)&kt,  g_kt);
    cudaGetSymbolAddress((void**)&vt,  g_vt);
    cudaGetSymbolAddress((void**)&wqt, g_wq);
    cudaGetSymbolAddress((void**)&wkt, g_wk);
    cudaGetSymbolAddress((void**)&wvt, g_wv);
    cudaGetSymbolAddress((void**)&wot, g_wo);
    cudaGetSymbolAddress((void**)&qh,  g_qh);
    cudaGetSymbolAddress((void**)&kh,  g_kh);
    cudaGetSymbolAddress((void**)&vh,  g_vh);
    cudaGetSymbolAddress((void**)&ao,  g_ao);

    const int flash_smem = (8192 + 4096 + 4096 + 4096 + 8192) * 4;  /* 114688 */
    cudaFuncSetAttribute(gemm_qkv,  cudaFuncAttributeMaxDynamicSharedMemorySize, GEMM_SMEM);
    cudaFuncSetAttribute(gemm_out,  cudaFuncAttributeMaxDynamicSharedMemorySize, GEMM_SMEM);
    cudaFuncSetAttribute(flash_attn, cudaFuncAttributeMaxDynamicSharedMemorySize, flash_smem);

    /* fused fp32 -> tf32 pre-conversion */
    dim3 gcvt(MROWS * DIM / 4 / 256, 7);     /* 4096 x 7 */
    cvt_all_kernel<<<gcvt, 256>>>(q, k, v, wq, wk, wv, wo,
                                  qt, kt, vt, wqt, wkt, wvt, wot);

    dim3 gqkv(DIM / BN, MROWS / BM, 3);        /* 4 x 32 x 3 */
    gemm_qkv<<<gqkv, 256, GEMM_SMEM>>>(qt, kt, vt, wqt, wkt, wvt, qh, kh, vh);

    flash_attn<<<dim3(SEQ / 128, BATCH * NH), 128, flash_smem>>>(qh, kh, vh, ao);

    dim3 gout(DIM / BN, MROWS / BM);           /* 4 x 32 */
    gemm_out<<<gout, 256, GEMM_SMEM>>>(ao, wot, (float*)d_out);
}

// round 8
// speedup vs baseline: 1.1144x; 1.0290x over previous
#include <cuda_runtime.h>
#include <cstdint>

#define DIM   1024
#define SEQ   2048
#define BATCH 2
#define NH    16
#define HD    64
#define MROWS (BATCH*SEQ)   /* 4096 */

/* ---------------- scratch (device globals: allocation-free) -------------- */
__device__ uint32_t g_qt[MROWS*DIM];      /* tf32 bits of q,k,v inputs */
__device__ uint32_t g_kt[MROWS*DIM];
__device__ uint32_t g_vt[MROWS*DIM];
__device__ uint32_t g_wq[DIM*DIM];        /* tf32 bits of weights */
__device__ uint32_t g_wk[DIM*DIM];
__device__ uint32_t g_wv[DIM*DIM];
__device__ uint32_t g_wo[DIM*DIM];
__device__ uint32_t g_qh[BATCH*NH*SEQ*HD];  /* tf32 [B,H,S,hd], pre-scaled */
__device__ uint32_t g_kh[BATCH*NH*SEQ*HD];
__device__ uint32_t g_vh[BATCH*NH*SEQ*HD];
__device__ uint32_t g_ao[MROWS*DIM];        /* tf32 [B*S, D] attn output */

__device__ __forceinline__ uint32_t f32_tf32(float f) {
    uint32_t r;
    asm("cvt.rna.tf32.f32 %0, %1;" : "=r"(r) : "f"(f));
    return r;
}
__device__ __forceinline__ float ex2f(float x) {
    float r;
    asm("ex2.approx.ftz.f32 %0, %1;" : "=f"(r) : "f"(x));
    return r;
}

__device__ __forceinline__ void mma_tf32(float* d, const uint32_t* a, const uint32_t* b) {
    asm volatile(
        "mma.sync.aligned.m16n8k8.row.col.f32.tf32.tf32.f32 "
        "{%0,%1,%2,%3}, {%4,%5,%6,%7}, {%8,%9}, {%0,%1,%2,%3};\n"
        : "+f"(d[0]), "+f"(d[1]), "+f"(d[2]), "+f"(d[3])
        : "r"(a[0]), "r"(a[1]), "r"(a[2]), "r"(a[3]), "r"(b[0]), "r"(b[1]));
}

__device__ __forceinline__ void cp16(uint32_t* smem_dst, const uint32_t* gsrc) {
    uint32_t sa = (uint32_t)__cvta_generic_to_shared(smem_dst);
    asm volatile("cp.async.cg.shared.global [%0], [%1], 16;"
                 :: "r"(sa), "l"(gsrc) : "memory");
}
#define CP_COMMIT() asm volatile("cp.async.commit_group;" ::: "memory")
#define CP_WAIT(n)  asm volatile("cp.async.wait_group %0;" :: "n"(n) : "memory")

/* ------------------- fused fp32 -> tf32 bits convert --------------------- */
__global__ __launch_bounds__(256) void cvt_all_kernel(
    const float* __restrict__ s0, const float* __restrict__ s1,
    const float* __restrict__ s2, const float* __restrict__ s3,
    const float* __restrict__ s4, const float* __restrict__ s5,
    const float* __restrict__ s6,
    uint32_t* __restrict__ d0, uint32_t* __restrict__ d1,
    uint32_t* __restrict__ d2, uint32_t* __restrict__ d3,
    uint32_t* __restrict__ d4, uint32_t* __restrict__ d5,
    uint32_t* __restrict__ d6)
{
    const float* srcs[7] = { s0, s1, s2, s3, s4, s5, s6 };
    uint32_t*    dsts[7] = { d0, d1, d2, d3, d4, d5, d6 };
    const int ns[7] = { MROWS*DIM/4, MROWS*DIM/4, MROWS*DIM/4,
                        DIM*DIM/4, DIM*DIM/4, DIM*DIM/4, DIM*DIM/4 };
    const int t = blockIdx.y;
    const int i = blockIdx.x * 256 + threadIdx.x;
    if (i < ns[t]) {
        float4 v = *(const float4*)(srcs[t] + (size_t)i * 4);
        *(uint4*)(dsts[t] + (size_t)i * 4) = make_uint4(
            f32_tf32(v.x), f32_tf32(v.y), f32_tf32(v.z), f32_tf32(v.w));
    }
}

/* =================== tf32 GEMM: C = A @ W^T =============================== */
#define BM 128
#define BN 256
#define BK 32
#define NKT (DIM / BK)
#define A_U32 (BM * BK)            /* 4096  */
#define B_U32 (BN * BK)            /* 8192  */
#define STG_U32 (A_U32 + B_U32)    /* 12288 */
#define NSTAGE 4
#define GEMM_SMEM (NSTAGE * STG_U32 * 4)  /* 196608 B */

__device__ __forceinline__ int swz(int row, int k) {
    return row * BK + (k ^ ((row & 7) << 2));
}

__device__ __forceinline__ void stage_async(
    uint32_t* __restrict__ As, uint32_t* __restrict__ Bs,
    const uint32_t* __restrict__ A, const uint32_t* __restrict__ W,
    int m0, int n0, int kc, int tid)
{
#pragma unroll
    for (int i = 0; i < 4; i++) {
        int f = tid + (i << 8);
        int row = f >> 3, c4 = (f & 7) << 2;
        cp16(As + swz(row, c4), A + (size_t)(m0 + row) * DIM + kc + c4);
    }
#pragma unroll
    for (int i = 0; i < 8; i++) {
        int f = tid + (i << 8);
        int row = f >> 3, c4 = (f & 7) << 2;
        cp16(Bs + swz(row, c4), W + (size_t)(n0 + row) * DIM + kc + c4);
    }
}

__device__ __forceinline__ void gemm_body(
    const uint32_t* __restrict__ A, const uint32_t* __restrict__ W,
    float* __restrict__ Cf, uint32_t* __restrict__ Ch, int mode, float scale)
{
    extern __shared__ uint32_t smg[];

    const int tid  = threadIdx.x;
    const int lane = tid & 31;
    const int wid  = tid >> 5;
    const int wm0  = (wid & 1) << 6;
    const int wn0  = (wid >> 1) << 6;
    const int m0   = blockIdx.y * BM;
    const int n0   = blockIdx.x * BN;
    const int r0   = lane >> 2;
    const int tig  = lane & 3;

    float acc[4][8][4];
#pragma unroll
    for (int mt = 0; mt < 4; mt++)
#pragma unroll
        for (int nt = 0; nt < 8; nt++)
#pragma unroll
            for (int e = 0; e < 4; e++) acc[mt][nt][e] = 0.f;

#pragma unroll
    for (int p = 0; p < NSTAGE - 1; p++) {
        stage_async(smg + p * STG_U32, smg + p * STG_U32 + A_U32,
                    A, W, m0, n0, p * BK, tid);
        CP_COMMIT();
    }

    for (int kt = 0; kt < NKT; kt++) {
        CP_WAIT(NSTAGE - 2);
        __syncthreads();

        if (kt + NSTAGE - 1 < NKT) {
            const int w = (kt + NSTAGE - 1) % NSTAGE;
            stage_async(smg + w * STG_U32, smg + w * STG_U32 + A_U32,
                        A, W, m0, n0, (kt + NSTAGE - 1) * BK, tid);
        }
        CP_COMMIT();

        const uint32_t* __restrict__ Ab = smg + (kt % NSTAGE) * STG_U32;
        const uint32_t* __restrict__ Bb = Ab + A_U32;
#pragma unroll
        for (int ks = 0; ks < 4; ks++) {
            const int k = (ks << 3) + tig;
            uint32_t af[4][4], bf[8][2];
#pragma unroll
            for (int mt = 0; mt < 4; mt++) {
                int row = wm0 + (mt << 4) + r0;
                af[mt][0] = Ab[swz(row,     k)];
                af[mt][1] = Ab[swz(row + 8, k)];
                af[mt][2] = Ab[swz(row,     k + 4)];
                af[mt][3] = Ab[swz(row + 8, k + 4)];
            }
#pragma unroll
            for (int nt = 0; nt < 8; nt++) {
                int n = wn0 + (nt << 3) + r0;
                bf[nt][0] = Bb[swz(n, k)];
                bf[nt][1] = Bb[swz(n, k + 4)];
            }
#pragma unroll
            for (int mt = 0; mt < 4; mt++)
#pragma unroll
                for (int nt = 0; nt < 8; nt++)
                    mma_tf32(acc[mt][nt], af[mt], bf[nt]);
        }
    }

#pragma unroll
    for (int mt = 0; mt < 4; mt++) {
#pragma unroll
        for (int half = 0; half < 2; half++) {
            const int m = m0 + wm0 + (mt << 4) + r0 + (half << 3);
            if (mode == 1) {
                const int b = m >> 11, srow = m & (SEQ - 1);
#pragma unroll
                for (int nt = 0; nt < 8; nt++) {
                    int col = n0 + wn0 + (nt << 3) + (tig << 1);
                    int h = col >> 6, dd = col & 63;
                    uint2 val = make_uint2(
                        f32_tf32(acc[mt][nt][half * 2]     * scale),
                        f32_tf32(acc[mt][nt][half * 2 + 1] * scale));
                    *(uint2*)(Ch + ((size_t)((b * NH + h) * SEQ + srow) << 6) + dd) = val;
                }
            } else {
#pragma unroll
                for (int nt = 0; nt < 8; nt++) {
                    int col = n0 + wn0 + (nt << 3) + (tig << 1);
                    float2 val = make_float2(acc[mt][nt][half * 2],
                                             acc[mt][nt][half * 2 + 1]);
                    *(float2*)(Cf + (size_t)m * DIM + col) = val;
                }
            }
        }
    }
}

__global__ __launch_bounds__(256) void gemm_qkv(
    const uint32_t* __restrict__ qt, const uint32_t* __restrict__ kt_,
    const uint32_t* __restrict__ vt, const uint32_t* __restrict__ wq,
    const uint32_t* __restrict__ wk, const uint32_t* __restrict__ wv,
    uint32_t* __restrict__ qh, uint32_t* __restrict__ kh, uint32_t* __restrict__ vh)
{
    const uint32_t* A; const uint32_t* W; uint32_t* C; float scale;
    /* Q pre-scaled by log2(e)/sqrt(hd) so softmax can use ex2 */
    if (blockIdx.z == 0)      { A = qt;  W = wq; C = qh; scale = 0.125f * 1.44269504f; }
    else if (blockIdx.z == 1) { A = kt_; W = wk; C = kh; scale = 1.0f; }
    else                      { A = vt;  W = wv; C = vh; scale = 1.0f; }
    gemm_body(A, W, nullptr, C, 1, scale);
}

__global__ __launch_bounds__(256) void gemm_out(
    const uint32_t* __restrict__ A, const uint32_t* __restrict__ W,
    float* __restrict__ C)
{
    gemm_body(A, W, C, nullptr, 0, 1.0f);
}

/* ============ tensor-core flash attention (causal), tf32 mma ==============
   Q fragments register-resident; K,V double-buffered; 1 sync per k-tile.
   SMEM: K0 16K | K1 16K | V0 16K | V1 16K | P 32K = 96 KB -> 2 CTA/SM.     */
#define SW64(row, k) ((row) * 64 + ((k) ^ (((row) & 7) << 3)))

__global__ __launch_bounds__(128) void flash_attn(
    const uint32_t* __restrict__ Qh, const uint32_t* __restrict__ Kh,
    const uint32_t* __restrict__ Vh, uint32_t* __restrict__ AO)
{
    extern __shared__ uint32_t fsm[];
    uint32_t* Ksb[2] = { fsm,         fsm + 4096  };
    uint32_t* Vsb[2] = { fsm + 8192,  fsm + 12288 };
    uint32_t* Ps     = fsm + 16384;   /* 128x64; doubles as Q staging */

    const int bh = blockIdx.y;
    const int qt = gridDim.x - 1 - blockIdx.x;   /* heavy tiles first */
    const int q0 = qt * 128;
    const uint32_t* Qb = Qh + (size_t)bh * SEQ * HD;
    const uint32_t* Kb = Kh + (size_t)bh * SEQ * HD;
    const uint32_t* Vb = Vh + (size_t)bh * SEQ * HD;

    const int tid  = threadIdx.x;
    const int lane = tid & 31;
    const int wid  = tid >> 5;
    const int r0   = lane >> 2;
    const int tig  = lane & 3;
    const int wq   = wid << 5;

    /* group: Q staging into Ps */
#pragma unroll
    for (int i = 0; i < 16; i++) {
        int f = tid + (i << 7);
        int row = f >> 4, c4 = (f & 15) << 2;
        cp16(Ps + SW64(row, c4), Qb + (size_t)(q0 + row) * HD + c4);
    }
    CP_COMMIT();
    /* group: K[0] + V[0] */
#pragma unroll
    for (int i = 0; i < 8; i++) {
        int f = tid + (i << 7);
        int row = f >> 4, c4 = (f & 15) << 2;
        cp16(Ksb[0] + SW64(row, c4), Kb + (size_t)row * HD + c4);
    }
#pragma unroll
    for (int i = 0; i < 8; i++) {
        int f = tid + (i << 7);
        int row = f >> 4, c4 = (f & 15) << 2;
        cp16(Vsb[0] + SW64(row, c4), Vb + (size_t)row * HD + c4);
    }
    CP_COMMIT();

    CP_WAIT(1);              /* Q staged; K0/V0 still in flight */
    __syncthreads();

    /* extract this warp's Q fragments to registers (reused all tiles) */
    uint32_t qf[8][2][4];
#pragma unroll
    for (int ks = 0; ks < 8; ks++) {
        const int k = (ks << 3) + tig;
#pragma unroll
        for (int mt = 0; mt < 2; mt++) {
            int row = wq + (mt << 4) + r0;
            qf[ks][mt][0] = Ps[SW64(row,     k)];
            qf[ks][mt][1] = Ps[SW64(row + 8, k)];
            qf[ks][mt][2] = Ps[SW64(row,     k + 4)];
            qf[ks][mt][3] = Ps[SW64(row + 8, k + 4)];
        }
    }
    __syncwarp();   /* warp w only rewrites its own P rows later */

    float o[2][8][4];
    float mi[4], li[4];
#pragma unroll
    for (int i = 0; i < 4; i++) { mi[i] = -1e30f; li[i] = 0.f; }
#pragma unroll
    for (int mt = 0; mt < 2; mt++)
#pragma unroll
        for (int nt = 0; nt < 8; nt++)
#pragma unroll
            for (int e = 0; e < 4; e++) o[mt][nt][e] = 0.f;

    const int nkt = 2 * qt + 2;
    for (int kt = 0; kt < nkt; kt++) {
        const int k0 = kt << 6;

        CP_WAIT(0);            /* K[kt],V[kt] resident */
        __syncthreads();       /* all warps done with buffers (kt-1) */

        /* prefetch K[kt+1],V[kt+1] — overlaps compute below */
        if (kt + 1 < nkt) {
            const uint32_t* Kp = Kb + (size_t)(k0 + 64) * HD;
            const uint32_t* Vp = Vb + (size_t)(k0 + 64) * HD;
            uint32_t* Kd = Ksb[(kt + 1) & 1];
            uint32_t* Vd = Vsb[(kt + 1) & 1];
#pragma unroll
            for (int i = 0; i < 8; i++) {
                int f = tid + (i << 7);
                int row = f >> 4, c4 = (f & 15) << 2;
                cp16(Kd + SW64(row, c4), Kp + (size_t)row * HD + c4);
            }
#pragma unroll
            for (int i = 0; i < 8; i++) {
                int f = tid + (i << 7);
                int row = f >> 4, c4 = (f & 15) << 2;
                cp16(Vd + SW64(row, c4), Vp + (size_t)row * HD + c4);
            }
            CP_COMMIT();
        }

        const uint32_t* Ks = Ksb[kt & 1];
        const uint32_t* Vs = Vsb[kt & 1];
        const bool active = (k0 <= q0 + wq + 31);
        if (active) {
            /* S = Q K^T (A from registers) */
            float s[2][8][4];
#pragma unroll
            for (int mt = 0; mt < 2; mt++)
#pragma unroll
                for (int nt = 0; nt < 8; nt++)
#pragma unroll
                    for (int e = 0; e < 4; e++) s[mt][nt][e] = 0.f;

#pragma unroll
            for (int ks = 0; ks < 8; ks++) {
                const int k = (ks << 3) + tig;
                uint32_t bf[8][2];
#pragma unroll
                for (int nt = 0; nt < 8; nt++) {
                    int n = (nt << 3) + r0;
                    bf[nt][0] = Ks[SW64(n, k)];
                    bf[nt][1] = Ks[SW64(n, k + 4)];
                }
#pragma unroll
                for (int mt = 0; mt < 2; mt++)
#pragma unroll
                    for (int nt = 0; nt < 8; nt++)
                        mma_tf32(s[mt][nt], qf[ks][mt], bf[nt]);
            }

            if (k0 + 63 > q0 + wq) {
#pragma unroll
                for (int mt = 0; mt < 2; mt++)
#pragma unroll
                    for (int nt = 0; nt < 8; nt++)
#pragma unroll
                        for (int e = 0; e < 4; e++) {
                            int rg = q0 + wq + (mt << 4) + ((e >> 1) << 3) + r0;
                            int cg = k0 + (nt << 3) + (tig << 1) + (e & 1);
                            if (cg > rg) s[mt][nt][e] = -1e30f;
                        }
            }

            /* online softmax (base-2 domain; Q pre-scaled by log2 e) */
#pragma unroll
            for (int mt = 0; mt < 2; mt++) {
#pragma unroll
                for (int half = 0; half < 2; half++) {
                    const int ri = mt * 2 + half;
                    float mx = -1e30f;
#pragma unroll
                    for (int nt = 0; nt < 8; nt++)
                        mx = fmaxf(mx, fmaxf(s[mt][nt][half*2], s[mt][nt][half*2+1]));
                    mx = fmaxf(mx, __shfl_xor_sync(0xffffffffu, mx, 1));
                    mx = fmaxf(mx, __shfl_xor_sync(0xffffffffu, mx, 2));
                    float mnew = fmaxf(mi[ri], mx);
                    float corr = ex2f(mi[ri] - mnew);
                    float sum = 0.f;
                    const int prow = wq + (mt << 4) + (half << 3) + r0;
#pragma unroll
                    for (int nt = 0; nt < 8; nt++) {
                        float p0 = ex2f(s[mt][nt][half*2]     - mnew);
                        float p1 = ex2f(s[mt][nt][half*2 + 1] - mnew);
                        sum += p0 + p1;
                        *(uint2*)(Ps + SW64(prow, (nt << 3) + (tig << 1))) =
                            make_uint2(f32_tf32(p0), f32_tf32(p1));
                    }
                    sum += __shfl_xor_sync(0xffffffffu, sum, 1);
                    sum += __shfl_xor_sync(0xffffffffu, sum, 2);
                    li[ri] = li[ri] * corr + sum;
                    mi[ri] = mnew;
#pragma unroll
                    for (int nt = 0; nt < 8; nt++) {
                        o[mt][nt][half*2]     *= corr;
                        o[mt][nt][half*2 + 1] *= corr;
                    }
                }
            }
            __syncwarp();

            /* O += P V ; B from Vs[key][hd]: b(n,k) = Vs[k][n] */
#pragma unroll
            for (int ks = 0; ks < 8; ks++) {
                const int k = (ks << 3) + tig;
                uint32_t af[2][4], bf[8][2];
#pragma unroll
                for (int mt = 0; mt < 2; mt++) {
                    int row = wq + (mt << 4) + r0;
                    af[mt][0] = Ps[SW64(row,     k)];
                    af[mt][1] = Ps[SW64(row + 8, k)];
                    af[mt][2] = Ps[SW64(row,     k + 4)];
                    af[mt][3] = Ps[SW64(row + 8, k + 4)];
                }
#pragma unroll
                for (int nt = 0; nt < 8; nt++) {
                    int n = (nt << 3) + r0;
                    bf[nt][0] = Vs[SW64(k,     n)];
                    bf[nt][1] = Vs[SW64(k + 4, n)];
                }
#pragma unroll
                for (int mt = 0; mt < 2; mt++)
#pragma unroll
                    for (int nt = 0; nt < 8; nt++)
                        mma_tf32(o[mt][nt], af[mt], bf[nt]);
            }
        }
        /* no trailing sync: next iteration's wait+sync protects buffers */
    }

    /* epilogue: normalize, store tf32 bits into AO */
    const int b = bh >> 4, h = bh & 15;
#pragma unroll
    for (int mt = 0; mt < 2; mt++) {
#pragma unroll
        for (int half = 0; half < 2; half++) {
            const float inv = 1.f / li[mt * 2 + half];
            const int rg = q0 + wq + (mt << 4) + (half << 3) + r0;
            uint32_t* row = AO + (size_t)(b * SEQ + rg) * DIM + (h << 6);
#pragma unroll
            for (int nt = 0; nt < 8; nt++) {
                *(uint2*)(row + (nt << 3) + (tig << 1)) = make_uint2(
                    f32_tf32(o[mt][nt][half*2] * inv),
                    f32_tf32(o[mt][nt][half*2 + 1] * inv));
            }
        }
    }
}

/* ---------------- launch -------------------------------------------------- */
extern "C" void kernel_launch(void* const* d_in, const int* in_sizes, int n_in,
                              void* d_out, int out_size)
{
    const float* q  = (const float*)d_in[0];
    const float* k  = (const float*)d_in[1];
    const float* v  = (const float*)d_in[2];
    const float* wq = (const float*)d_in[3];
    const float* wk = (const float*)d_in[4];
    const float* wv = (const float*)d_in[5];
    const float* wo = (const float*)d_in[6];

    uint32_t *qt, *kt, *vt, *wqt, *wkt, *wvt, *wot, *qh, *kh, *vh, *ao;
    cudaGetSymbolAddress((void**)&qt,  g_qt);
    cudaGetSymbolAddress((void**)&kt,  g_kt);
    cudaGetSymbolAddress((void**)&vt,  g_vt);
    cudaGetSymbolAddress((void**)&wqt, g_wq);
    cudaGetSymbolAddress((void**)&wkt, g_wk);
    cudaGetSymbolAddress((void**)&wvt, g_wv);
    cudaGetSymbolAddress((void**)&wot, g_wo);
    cudaGetSymbolAddress((void**)&qh,  g_qh);
    cudaGetSymbolAddress((void**)&kh,  g_kh);
    cudaGetSymbolAddress((void**)&vh,  g_vh);
    cudaGetSymbolAddress((void**)&ao,  g_ao);

    const int flash_smem = (4096 * 4 + 8192) * 4;   /* 98304 */
    cudaFuncSetAttribute(gemm_qkv,  cudaFuncAttributeMaxDynamicSharedMemorySize, GEMM_SMEM);
    cudaFuncSetAttribute(gemm_out,  cudaFuncAttributeMaxDynamicSharedMemorySize, GEMM_SMEM);
    cudaFuncSetAttribute(flash_attn, cudaFuncAttributeMaxDynamicSharedMemorySize, flash_smem);

    /* fused fp32 -> tf32 pre-conversion */
    dim3 gcvt(MROWS * DIM / 4 / 256, 7);     /* 4096 x 7 */
    cvt_all_kernel<<<gcvt, 256>>>(q, k, v, wq, wk, wv, wo,
                                  qt, kt, vt, wqt, wkt, wvt, wot);

    dim3 gqkv(DIM / BN, MROWS / BM, 3);        /* 4 x 32 x 3 */
    gemm_qkv<<<gqkv, 256, GEMM_SMEM>>>(qt, kt, vt, wqt, wkt, wvt, qh, kh, vh);

    flash_attn<<<dim3(SEQ / 128, BATCH * NH), 128, flash_smem>>>(qh, kh, vh, ao);

    dim3 gout(DIM / BN, MROWS / BM);           /* 4 x 32 */
    gemm_out<<<gout, 256, GEMM_SMEM>>>(ao, wot, (float*)d_out);
}

// round 9
// speedup vs baseline: 1.8999x; 1.7048x over previous
#include <cuda_runtime.h>
#include <cuda_fp16.h>
#include <cstdint>

#define DIM   1024
#define SEQ   2048
#define BATCH 2
#define NH    16
#define HD    64
#define MROWS (BATCH*SEQ)   /* 4096 */

/* ------------- scratch (device globals, fp16 packed as u32) -------------- */
__device__ uint32_t g_qt[MROWS*DIM/2];
__device__ uint32_t g_kt[MROWS*DIM/2];
__device__ uint32_t g_vt[MROWS*DIM/2];
__device__ uint32_t g_wq[DIM*DIM/2];
__device__ uint32_t g_wk[DIM*DIM/2];
__device__ uint32_t g_wv[DIM*DIM/2];
__device__ uint32_t g_wo[DIM*DIM/2];
__device__ uint32_t g_qh[BATCH*NH*SEQ*HD/2];  /* [B,H,S,hd/2], Q pre-scaled */
__device__ uint32_t g_kh[BATCH*NH*SEQ*HD/2];
__device__ uint32_t g_vh[BATCH*NH*SEQ*HD/2];
__device__ uint32_t g_ao[MROWS*DIM/2];        /* [B*S, D/2] attn output */

__device__ __forceinline__ uint32_t h2pack(float lo, float hi) {
    __half2 h = __floats2half2_rn(lo, hi);
    return *(uint32_t*)&h;
}
__device__ __forceinline__ float ex2f(float x) {
    float r;
    asm("ex2.approx.ftz.f32 %0, %1;" : "=f"(r) : "f"(x));
    return r;
}

__device__ __forceinline__ void mma_f16(float* d, const uint32_t* a, const uint32_t* b) {
    asm volatile(
        "mma.sync.aligned.m16n8k16.row.col.f32.f16.f16.f32 "
        "{%0,%1,%2,%3}, {%4,%5,%6,%7}, {%8,%9}, {%0,%1,%2,%3};\n"
        : "+f"(d[0]), "+f"(d[1]), "+f"(d[2]), "+f"(d[3])
        : "r"(a[0]), "r"(a[1]), "r"(a[2]), "r"(a[3]), "r"(b[0]), "r"(b[1]));
}

__device__ __forceinline__ void cp16(uint32_t* smem_dst, const uint32_t* gsrc) {
    uint32_t sa = (uint32_t)__cvta_generic_to_shared(smem_dst);
    asm volatile("cp.async.cg.shared.global [%0], [%1], 16;"
                 :: "r"(sa), "l"(gsrc) : "memory");
}
#define CP_COMMIT() asm volatile("cp.async.commit_group;" ::: "memory")
#define CP_WAIT(n)  asm volatile("cp.async.wait_group %0;" :: "n"(n) : "memory")

/* xor swizzle for 32-u32 (64-half) rows: 16B-aligned, conflict-free        */
#define SWZ32(row, c) ((row) * 32 + ((c) ^ (((row) & 7) << 2)))

/* ------------------- fused fp32 -> fp16 convert --------------------------- */
__global__ __launch_bounds__(256) void cvt_all_kernel(
    const float* __restrict__ s0, const float* __restrict__ s1,
    const float* __restrict__ s2, const float* __restrict__ s3,
    const float* __restrict__ s4, const float* __restrict__ s5,
    const float* __restrict__ s6,
    uint32_t* __restrict__ d0, uint32_t* __restrict__ d1,
    uint32_t* __restrict__ d2, uint32_t* __restrict__ d3,
    uint32_t* __restrict__ d4, uint32_t* __restrict__ d5,
    uint32_t* __restrict__ d6)
{
    const float* srcs[7] = { s0, s1, s2, s3, s4, s5, s6 };
    uint32_t*    dsts[7] = { d0, d1, d2, d3, d4, d5, d6 };
    const int ns[7] = { MROWS*DIM/4, MROWS*DIM/4, MROWS*DIM/4,
                        DIM*DIM/4, DIM*DIM/4, DIM*DIM/4, DIM*DIM/4 };
    const int t = blockIdx.y;
    const int i = blockIdx.x * 256 + threadIdx.x;
    if (i < ns[t]) {
        float4 v = *(const float4*)(srcs[t] + (size_t)i * 4);
        uint2 o = make_uint2(h2pack(v.x, v.y), h2pack(v.z, v.w));
        *(uint2*)(dsts[t] + (size_t)i * 2) = o;
    }
}

/* =================== fp16 GEMM: C = A @ W^T =============================== */
/* block 128x256, BK=64 halves (32 u32), 256 thr / 8 warps, 3-stage async   */
#define BM 128
#define BN 256
#define BKH 64                      /* halves per k-tile */
#define NKT (DIM / BKH)             /* 16 */
#define ROWU 32                     /* u32 per tile row */
#define A_U32 (BM * ROWU)           /* 4096  */
#define B_U32 (BN * ROWU)           /* 8192  */
#define STG_U32 (A_U32 + B_U32)     /* 12288 */
#define NSTAGE 3
#define GEMM_SMEM (NSTAGE * STG_U32 * 4)  /* 147456 B */
#define GSTRIDE (DIM / 2)           /* 512 u32 per gmem row */

__device__ __forceinline__ void stage_async(
    uint32_t* __restrict__ As, uint32_t* __restrict__ Bs,
    const uint32_t* __restrict__ A, const uint32_t* __restrict__ W,
    int m0, int n0, int kc /* u32 units */, int tid)
{
#pragma unroll
    for (int i = 0; i < 4; i++) {            /* A: 128 rows x 32 u32 */
        int f = tid + (i << 8);
        int row = f >> 3, c4 = (f & 7) << 2;
        cp16(As + SWZ32(row, c4), A + (size_t)(m0 + row) * GSTRIDE + kc + c4);
    }
#pragma unroll
    for (int i = 0; i < 8; i++) {            /* B: 256 rows x 32 u32 */
        int f = tid + (i << 8);
        int row = f >> 3, c4 = (f & 7) << 2;
        cp16(Bs + SWZ32(row, c4), W + (size_t)(n0 + row) * GSTRIDE + kc + c4);
    }
}

__device__ __forceinline__ void gemm_body(
    const uint32_t* __restrict__ A, const uint32_t* __restrict__ W,
    float* __restrict__ Cf, uint32_t* __restrict__ Ch, int mode, float scale)
{
    extern __shared__ uint32_t smg[];

    const int tid  = threadIdx.x;
    const int lane = tid & 31;
    const int wid  = tid >> 5;
    const int wm0  = (wid & 1) << 6;
    const int wn0  = (wid >> 1) << 6;
    const int m0   = blockIdx.y * BM;
    const int n0   = blockIdx.x * BN;
    const int r0   = lane >> 2;
    const int tig  = lane & 3;

    float acc[4][8][4];
#pragma unroll
    for (int mt = 0; mt < 4; mt++)
#pragma unroll
        for (int nt = 0; nt < 8; nt++)
#pragma unroll
            for (int e = 0; e < 4; e++) acc[mt][nt][e] = 0.f;

#pragma unroll
    for (int p = 0; p < NSTAGE - 1; p++) {
        stage_async(smg + p * STG_U32, smg + p * STG_U32 + A_U32,
                    A, W, m0, n0, p * ROWU, tid);
        CP_COMMIT();
    }

    for (int kt = 0; kt < NKT; kt++) {
        CP_WAIT(NSTAGE - 2);
        __syncthreads();

        if (kt + NSTAGE - 1 < NKT) {
            const int w = (kt + NSTAGE - 1) % NSTAGE;
            stage_async(smg + w * STG_U32, smg + w * STG_U32 + A_U32,
                        A, W, m0, n0, (kt + NSTAGE - 1) * ROWU, tid);
        }
        CP_COMMIT();

        const uint32_t* __restrict__ Ab = smg + (kt % NSTAGE) * STG_U32;
        const uint32_t* __restrict__ Bb = Ab + A_U32;
#pragma unroll
        for (int ks = 0; ks < 4; ks++) {     /* 4 x k16 per 64-half tile */
            const int kb = (ks << 3) + tig;
            uint32_t af[4][4], bf[8][2];
#pragma unroll
            for (int mt = 0; mt < 4; mt++) {
                int row = wm0 + (mt << 4) + r0;
                af[mt][0] = Ab[SWZ32(row,     kb)];
                af[mt][1] = Ab[SWZ32(row + 8, kb)];
                af[mt][2] = Ab[SWZ32(row,     kb + 4)];
                af[mt][3] = Ab[SWZ32(row + 8, kb + 4)];
            }
#pragma unroll
            for (int nt = 0; nt < 8; nt++) {
                int n = wn0 + (nt << 3) + r0;
                bf[nt][0] = Bb[SWZ32(n, kb)];
                bf[nt][1] = Bb[SWZ32(n, kb + 4)];
            }
#pragma unroll
            for (int mt = 0; mt < 4; mt++)
#pragma unroll
                for (int nt = 0; nt < 8; nt++)
                    mma_f16(acc[mt][nt], af[mt], bf[nt]);
        }
    }

#pragma unroll
    for (int mt = 0; mt < 4; mt++) {
#pragma unroll
        for (int half = 0; half < 2; half++) {
            const int m = m0 + wm0 + (mt << 4) + r0 + (half << 3);
            if (mode == 1) {
                const int b = m >> 11, srow = m & (SEQ - 1);
#pragma unroll
                for (int nt = 0; nt < 8; nt++) {
                    int col = n0 + wn0 + (nt << 3) + (tig << 1);
                    int h = col >> 6, dd = col & 63;
                    uint32_t val = h2pack(acc[mt][nt][half * 2]     * scale,
                                          acc[mt][nt][half * 2 + 1] * scale);
                    Ch[((size_t)((b * NH + h) * SEQ + srow) << 5) + (dd >> 1)] = val;
                }
            } else {
#pragma unroll
                for (int nt = 0; nt < 8; nt++) {
                    int col = n0 + wn0 + (nt << 3) + (tig << 1);
                    float2 val = make_float2(acc[mt][nt][half * 2],
                                             acc[mt][nt][half * 2 + 1]);
                    *(float2*)(Cf + (size_t)m * DIM + col) = val;
                }
            }
        }
    }
}

__global__ __launch_bounds__(256) void gemm_qkv(
    const uint32_t* __restrict__ qt, const uint32_t* __restrict__ kt_,
    const uint32_t* __restrict__ vt, const uint32_t* __restrict__ wq,
    const uint32_t* __restrict__ wk, const uint32_t* __restrict__ wv,
    uint32_t* __restrict__ qh, uint32_t* __restrict__ kh, uint32_t* __restrict__ vh)
{
    const uint32_t* A; const uint32_t* W; uint32_t* C; float scale;
    /* Q pre-scaled by log2(e)/sqrt(hd) for base-2 softmax */
    if (blockIdx.z == 0)      { A = qt;  W = wq; C = qh; scale = 0.125f * 1.44269504f; }
    else if (blockIdx.z == 1) { A = kt_; W = wk; C = kh; scale = 1.0f; }
    else                      { A = vt;  W = wv; C = vh; scale = 1.0f; }
    gemm_body(A, W, nullptr, C, 1, scale);
}

__global__ __launch_bounds__(256) void gemm_out(
    const uint32_t* __restrict__ A, const uint32_t* __restrict__ W,
    float* __restrict__ C)
{
    gemm_body(A, W, C, nullptr, 0, 1.0f);
}

/* ============ fp16 tensor-core flash attention (causal) ===================
   Q fragments register-resident; P stays in registers (acc->A-frag pack);
   V B-fragments via ldmatrix.x4.trans; K,V double-buffered, 1 sync/tile.
   SMEM: Q 16K | K0 8K | K1 8K | V0 8K | V1 8K = 48 KB.                     */

__global__ __launch_bounds__(128) void flash_attn(
    const uint32_t* __restrict__ Qh, const uint32_t* __restrict__ Kh,
    const uint32_t* __restrict__ Vh, uint32_t* __restrict__ AO)
{
    extern __shared__ uint32_t fsm[];
    uint32_t* Qs     = fsm;                       /* 128 x 32 u32 */
    uint32_t* Ksb[2] = { fsm + 4096, fsm + 6144 };/* 64 x 32 each */
    uint32_t* Vsb[2] = { fsm + 8192, fsm + 10240 };

    const int bh = blockIdx.y;
    const int qt = gridDim.x - 1 - blockIdx.x;    /* heavy tiles first */
    const int q0 = qt * 128;
    const uint32_t* Qb = Qh + (size_t)bh * SEQ * (HD/2);
    const uint32_t* Kb = Kh + (size_t)bh * SEQ * (HD/2);
    const uint32_t* Vb = Vh + (size_t)bh * SEQ * (HD/2);

    const int tid  = threadIdx.x;
    const int lane = tid & 31;
    const int wid  = tid >> 5;
    const int r0   = lane >> 2;
    const int tig  = lane & 3;
    const int wq   = wid << 5;

    /* ldmatrix lane constants */
    const int lm_g   = lane >> 3;                 /* group 0..3 */
    const int lm_key = ((lm_g & 1) << 3) + (lane & 7);
    const int lm_nt2 = lm_g >> 1;                 /* 0 or 1 */

    /* group A: Q tile (128 x 32 u32) */
#pragma unroll
    for (int i = 0; i < 8; i++) {
        int f = tid + (i << 7);
        int row = f >> 3, c4 = (f & 7) << 2;
        cp16(Qs + SWZ32(row, c4), Qb + (size_t)(q0 + row) * (HD/2) + c4);
    }
    CP_COMMIT();
    /* group B: K[0] + V[0] (64 x 32 u32 each) */
#pragma unroll
    for (int i = 0; i < 4; i++) {
        int f = tid + (i << 7);
        int row = f >> 3, c4 = (f & 7) << 2;
        cp16(Ksb[0] + SWZ32(row, c4), Kb + (size_t)row * (HD/2) + c4);
    }
#pragma unroll
    for (int i = 0; i < 4; i++) {
        int f = tid + (i << 7);
        int row = f >> 3, c4 = (f & 7) << 2;
        cp16(Vsb[0] + SWZ32(row, c4), Vb + (size_t)row * (HD/2) + c4);
    }
    CP_COMMIT();

    CP_WAIT(1);
    __syncthreads();

    /* Q fragments to registers: 4 k-steps x 2 mt x 4 regs */
    uint32_t qf[4][2][4];
#pragma unroll
    for (int ks = 0; ks < 4; ks++) {
        const int kb = (ks << 3) + tig;
#pragma unroll
        for (int mt = 0; mt < 2; mt++) {
            int row = wq + (mt << 4) + r0;
            qf[ks][mt][0] = Qs[SWZ32(row,     kb)];
            qf[ks][mt][1] = Qs[SWZ32(row + 8, kb)];
            qf[ks][mt][2] = Qs[SWZ32(row,     kb + 4)];
            qf[ks][mt][3] = Qs[SWZ32(row + 8, kb + 4)];
        }
    }

    float o[2][8][4];
    float mi[4], li[4];
#pragma unroll
    for (int i = 0; i < 4; i++) { mi[i] = -1e30f; li[i] = 0.f; }
#pragma unroll
    for (int mt = 0; mt < 2; mt++)
#pragma unroll
        for (int nt = 0; nt < 8; nt++)
#pragma unroll
            for (int e = 0; e < 4; e++) o[mt][nt][e] = 0.f;

    const int nkt = 2 * qt + 2;
    for (int kt = 0; kt < nkt; kt++) {
        const int k0 = kt << 6;

        CP_WAIT(0);
        __syncthreads();

        /* prefetch K/V[kt+1] — overlaps compute */
        if (kt + 1 < nkt) {
            const uint32_t* Kp = Kb + (size_t)(k0 + 64) * (HD/2);
            const uint32_t* Vp = Vb + (size_t)(k0 + 64) * (HD/2);
            uint32_t* Kd = Ksb[(kt + 1) & 1];
            uint32_t* Vd = Vsb[(kt + 1) & 1];
#pragma unroll
            for (int i = 0; i < 4; i++) {
                int f = tid + (i << 7);
                int row = f >> 3, c4 = (f & 7) << 2;
                cp16(Kd + SWZ32(row, c4), Kp + (size_t)row * (HD/2) + c4);
            }
#pragma unroll
            for (int i = 0; i < 4; i++) {
                int f = tid + (i << 7);
                int row = f >> 3, c4 = (f & 7) << 2;
                cp16(Vd + SWZ32(row, c4), Vp + (size_t)row * (HD/2) + c4);
            }
            CP_COMMIT();
        }

        const uint32_t* Ks = Ksb[kt & 1];
        const uint32_t* Vs = Vsb[kt & 1];
        const uint32_t vbase = (uint32_t)__cvta_generic_to_shared(Vs);
        const bool active = (k0 <= q0 + wq + 31);
        if (active) {
            /* S = Q K^T (A from regs, B direct LDS) */
            float s[2][8][4];
#pragma unroll
            for (int mt = 0; mt < 2; mt++)
#pragma unroll
                for (int nt = 0; nt < 8; nt++)
#pragma unroll
                    for (int e = 0; e < 4; e++) s[mt][nt][e] = 0.f;

#pragma unroll
            for (int ks = 0; ks < 4; ks++) {
                const int kb = (ks << 3) + tig;
                uint32_t bf[8][2];
#pragma unroll
                for (int nt = 0; nt < 8; nt++) {
                    int n = (nt << 3) + r0;
                    bf[nt][0] = Ks[SWZ32(n, kb)];
                    bf[nt][1] = Ks[SWZ32(n, kb + 4)];
                }
#pragma unroll
                for (int mt = 0; mt < 2; mt++)
#pragma unroll
                    for (int nt = 0; nt < 8; nt++)
                        mma_f16(s[mt][nt], qf[ks][mt], bf[nt]);
            }

            /* causal mask near diagonal */
            if (k0 + 63 > q0 + wq) {
#pragma unroll
                for (int mt = 0; mt < 2; mt++)
#pragma unroll
                    for (int nt = 0; nt < 8; nt++)
#pragma unroll
                        for (int e = 0; e < 4; e++) {
                            int rg = q0 + wq + (mt << 4) + ((e >> 1) << 3) + r0;
                            int cg = k0 + (nt << 3) + (tig << 1) + (e & 1);
                            if (cg > rg) s[mt][nt][e] = -1e30f;
                        }
            }

            /* online softmax (base-2); p kept in s[] as floats */
#pragma unroll
            for (int mt = 0; mt < 2; mt++) {
#pragma unroll
                for (int half = 0; half < 2; half++) {
                    const int ri = mt * 2 + half;
                    float mx = -1e30f;
#pragma unroll
                    for (int nt = 0; nt < 8; nt++)
                        mx = fmaxf(mx, fmaxf(s[mt][nt][half*2], s[mt][nt][half*2+1]));
                    mx = fmaxf(mx, __shfl_xor_sync(0xffffffffu, mx, 1));
                    mx = fmaxf(mx, __shfl_xor_sync(0xffffffffu, mx, 2));
                    float mnew = fmaxf(mi[ri], mx);
                    float corr = ex2f(mi[ri] - mnew);
                    float sum = 0.f;
#pragma unroll
                    for (int nt = 0; nt < 8; nt++) {
                        float p0 = ex2f(s[mt][nt][half*2]     - mnew);
                        float p1 = ex2f(s[mt][nt][half*2 + 1] - mnew);
                        s[mt][nt][half*2]     = p0;
                        s[mt][nt][half*2 + 1] = p1;
                        sum += p0 + p1;
                    }
                    sum += __shfl_xor_sync(0xffffffffu, sum, 1);
                    sum += __shfl_xor_sync(0xffffffffu, sum, 2);
                    li[ri] = li[ri] * corr + sum;
                    mi[ri] = mnew;
#pragma unroll
                    for (int nt = 0; nt < 8; nt++) {
                        o[mt][nt][half*2]     *= corr;
                        o[mt][nt][half*2 + 1] *= corr;
                    }
                }
            }

            /* O += P V : A from registers (pack), B via ldmatrix.trans */
#pragma unroll
            for (int ks = 0; ks < 4; ks++) {
                uint32_t bf[8][2];
#pragma unroll
                for (int j = 0; j < 4; j++) {
                    int key = (ks << 4) + lm_key;
                    int c   = ((j << 1) + lm_nt2) << 2;
                    uint32_t addr = vbase + 4u * (uint32_t)SWZ32(key, c);
                    uint32_t t0, t1, t2, t3;
                    asm volatile(
                        "ldmatrix.sync.aligned.m8n8.x4.trans.shared.b16 "
                        "{%0,%1,%2,%3}, [%4];"
                        : "=r"(t0), "=r"(t1), "=r"(t2), "=r"(t3) : "r"(addr));
                    bf[(j << 1)    ][0] = t0;
                    bf[(j << 1)    ][1] = t1;
                    bf[(j << 1) + 1][0] = t2;
                    bf[(j << 1) + 1][1] = t3;
                }
#pragma unroll
                for (int mt = 0; mt < 2; mt++) {
                    uint32_t af[4];
                    af[0] = h2pack(s[mt][2*ks    ][0], s[mt][2*ks    ][1]);
                    af[1] = h2pack(s[mt][2*ks    ][2], s[mt][2*ks    ][3]);
                    af[2] = h2pack(s[mt][2*ks + 1][0], s[mt][2*ks + 1][1]);
                    af[3] = h2pack(s[mt][2*ks + 1][2], s[mt][2*ks + 1][3]);
#pragma unroll
                    for (int nt = 0; nt < 8; nt++)
                        mma_f16(o[mt][nt], af, bf[nt]);
                }
            }
        }
        /* next iteration's wait+sync protects buffers */
    }

    /* epilogue: normalize, store packed fp16 into AO */
    const int b = bh >> 4, h = bh & 15;
#pragma unroll
    for (int mt = 0; mt < 2; mt++) {
#pragma unroll
        for (int half = 0; half < 2; half++) {
            const float inv = 1.f / li[mt * 2 + half];
            const int rg = q0 + wq + (mt << 4) + (half << 3) + r0;
            uint32_t* row = AO + (size_t)(b * SEQ + rg) * GSTRIDE + (h << 5);
#pragma unroll
            for (int nt = 0; nt < 8; nt++) {
                row[(nt << 2) + tig] = h2pack(o[mt][nt][half*2]     * inv,
                                              o[mt][nt][half*2 + 1] * inv);
            }
        }
    }
}

/* ---------------- launch -------------------------------------------------- */
extern "C" void kernel_launch(void* const* d_in, const int* in_sizes, int n_in,
                              void* d_out, int out_size)
{
    const float* q  = (const float*)d_in[0];
    const float* k  = (const float*)d_in[1];
    const float* v  = (const float*)d_in[2];
    const float* wq = (const float*)d_in[3];
    const float* wk = (const float*)d_in[4];
    const float* wv = (const float*)d_in[5];
    const float* wo = (const float*)d_in[6];

    uint32_t *qt, *kt, *vt, *wqt, *wkt, *wvt, *wot, *qh, *kh, *vh, *ao;
    cudaGetSymbolAddress((void**)&qt,  g_qt);
    cudaGetSymbolAddress((void**)&kt,  g_kt);
    cudaGetSymbolAddress((void**)&vt,  g_vt);
    cudaGetSymbolAddress((void**)&wqt, g_wq);
    cudaGetSymbolAddress((void**)&wkt, g_wk);
    cudaGetSymbolAddress((void**)&wvt, g_wv);
    cudaGetSymbolAddress((void**)&wot, g_wo);
    cudaGetSymbolAddress((void**)&qh,  g_qh);
    cudaGetSymbolAddress((void**)&kh,  g_kh);
    cudaGetSymbolAddress((void**)&vh,  g_vh);
    cudaGetSymbolAddress((void**)&ao,  g_ao);

    const int flash_smem = 12288 * 4;   /* 49152 */
    cudaFuncSetAttribute(gemm_qkv,  cudaFuncAttributeMaxDynamicSharedMemorySize, GEMM_SMEM);
    cudaFuncSetAttribute(gemm_out,  cudaFuncAttributeMaxDynamicSharedMemorySize, GEMM_SMEM);
    cudaFuncSetAttribute(flash_attn, cudaFuncAttributeMaxDynamicSharedMemorySize, flash_smem);

    /* fused fp32 -> fp16 pre-conversion */
    dim3 gcvt(MROWS * DIM / 4 / 256, 7);     /* 4096 x 7 */
    cvt_all_kernel<<<gcvt, 256>>>(q, k, v, wq, wk, wv, wo,
                                  qt, kt, vt, wqt, wkt, wvt, wot);

    dim3 gqkv(DIM / BN, MROWS / BM, 3);        /* 4 x 32 x 3 */
    gemm_qkv<<<gqkv, 256, GEMM_SMEM>>>(qt, kt, vt, wqt, wkt, wvt, qh, kh, vh);

    flash_attn<<<dim3(SEQ / 128, BATCH * NH), 128, flash_smem>>>(qh, kh, vh, ao);

    dim3 gout(DIM / BN, MROWS / BM);           /* 4 x 32 */
    gemm_out<<<gout, 256, GEMM_SMEM>>>(ao, wot, (float*)d_out);
}

// round 10
// speedup vs baseline: 1.9732x; 1.0386x over previous
#include <cuda_runtime.h>
#include <cuda_fp16.h>
#include <cstdint>

#define DIM   1024
#define SEQ   2048
#define BATCH 2
#define NH    16
#define HD    64
#define MROWS (BATCH*SEQ)   /* 4096 */

/* ------------- scratch (device globals, fp16 packed as u32) -------------- */
__device__ uint32_t g_qt[MROWS*DIM/2];
__device__ uint32_t g_kt[MROWS*DIM/2];
__device__ uint32_t g_vt[MROWS*DIM/2];
__device__ uint32_t g_wq[DIM*DIM/2];
__device__ uint32_t g_wk[DIM*DIM/2];
__device__ uint32_t g_wv[DIM*DIM/2];
__device__ uint32_t g_wo[DIM*DIM/2];
__device__ uint32_t g_qh[BATCH*NH*SEQ*HD/2];  /* [B,H,S,hd/2], Q pre-scaled */
__device__ uint32_t g_kh[BATCH*NH*SEQ*HD/2];
__device__ uint32_t g_vh[BATCH*NH*SEQ*HD/2];
__device__ uint32_t g_ao[MROWS*DIM/2];        /* [B*S, D/2] attn output */

__device__ __forceinline__ uint32_t h2pack(float lo, float hi) {
    __half2 h = __floats2half2_rn(lo, hi);
    return *(uint32_t*)&h;
}
__device__ __forceinline__ float ex2f(float x) {
    float r;
    asm("ex2.approx.ftz.f32 %0, %1;" : "=f"(r) : "f"(x));
    return r;
}
/* pack two f32 -> f16x2 (hi, lo) */
__device__ __forceinline__ uint32_t cvt_f16x2(float hi, float lo) {
    uint32_t r;
    asm("cvt.rn.f16x2.f32 %0, %1, %2;" : "=r"(r) : "f"(hi), "f"(lo));
    return r;
}
__device__ __forceinline__ uint32_t ex2_h2(uint32_t x) {
    uint32_t r;
    asm("ex2.approx.f16x2 %0, %1;" : "=r"(r) : "r"(x));
    return r;
}
__device__ __forceinline__ uint32_t hadd2u(uint32_t a, uint32_t b) {
    uint32_t r;
    asm("add.rn.f16x2 %0, %1, %2;" : "=r"(r) : "r"(a), "r"(b));
    return r;
}

__device__ __forceinline__ void mma_f16(float* d, const uint32_t* a, const uint32_t* b) {
    asm volatile(
        "mma.sync.aligned.m16n8k16.row.col.f32.f16.f16.f32 "
        "{%0,%1,%2,%3}, {%4,%5,%6,%7}, {%8,%9}, {%0,%1,%2,%3};\n"
        : "+f"(d[0]), "+f"(d[1]), "+f"(d[2]), "+f"(d[3])
        : "r"(a[0]), "r"(a[1]), "r"(a[2]), "r"(a[3]), "r"(b[0]), "r"(b[1]));
}

__device__ __forceinline__ void ldsm_x4(uint32_t& r0, uint32_t& r1,
                                        uint32_t& r2, uint32_t& r3, uint32_t addr) {
    asm volatile("ldmatrix.sync.aligned.m8n8.x4.shared.b16 {%0,%1,%2,%3}, [%4];"
                 : "=r"(r0), "=r"(r1), "=r"(r2), "=r"(r3) : "r"(addr));
}

__device__ __forceinline__ void cp16(uint32_t* smem_dst, const uint32_t* gsrc) {
    uint32_t sa = (uint32_t)__cvta_generic_to_shared(smem_dst);
    asm volatile("cp.async.cg.shared.global [%0], [%1], 16;"
                 :: "r"(sa), "l"(gsrc) : "memory");
}
#define CP_COMMIT() asm volatile("cp.async.commit_group;" ::: "memory")
#define CP_WAIT(n)  asm volatile("cp.async.wait_group %0;" :: "n"(n) : "memory")

/* xor swizzle for 32-u32 (64-half) rows: 16B-aligned, conflict-free        */
#define SWZ32(row, c) ((row) * 32 + ((c) ^ (((row) & 7) << 2)))

/* ------------------- fused fp32 -> fp16 convert --------------------------- */
__global__ __launch_bounds__(256) void cvt_all_kernel(
    const float* __restrict__ s0, const float* __restrict__ s1,
    const float* __restrict__ s2, const float* __restrict__ s3,
    const float* __restrict__ s4, const float* __restrict__ s5,
    const float* __restrict__ s6,
    uint32_t* __restrict__ d0, uint32_t* __restrict__ d1,
    uint32_t* __restrict__ d2, uint32_t* __restrict__ d3,
    uint32_t* __restrict__ d4, uint32_t* __restrict__ d5,
    uint32_t* __restrict__ d6)
{
    const float* srcs[7] = { s0, s1, s2, s3, s4, s5, s6 };
    uint32_t*    dsts[7] = { d0, d1, d2, d3, d4, d5, d6 };
    const int ns[7] = { MROWS*DIM/4, MROWS*DIM/4, MROWS*DIM/4,
                        DIM*DIM/4, DIM*DIM/4, DIM*DIM/4, DIM*DIM/4 };
    const int t = blockIdx.y;
    const int i = blockIdx.x * 256 + threadIdx.x;
    if (i < ns[t]) {
        float4 v = *(const float4*)(srcs[t] + (size_t)i * 4);
        uint2 o = make_uint2(h2pack(v.x, v.y), h2pack(v.z, v.w));
        *(uint2*)(dsts[t] + (size_t)i * 2) = o;
    }
}

/* =================== fp16 GEMM: C = A @ W^T =============================== */
#define BM 128
#define BN 256
#define NKT 16                      /* 16 k-tiles of 64 halves */
#define ROWU 32                     /* u32 per tile row */
#define A_U32 (BM * ROWU)           /* 4096  */
#define B_U32 (BN * ROWU)           /* 8192  */
#define STG_U32 (A_U32 + B_U32)     /* 12288 */
#define NSTAGE 3
#define GEMM_SMEM (NSTAGE * STG_U32 * 4)  /* 147456 B */
#define GSTRIDE (DIM / 2)           /* 512 u32 per gmem row */

__device__ __forceinline__ void stage_async(
    uint32_t* __restrict__ As, uint32_t* __restrict__ Bs,
    const uint32_t* __restrict__ A, const uint32_t* __restrict__ W,
    int m0, int n0, int kc, int tid)
{
#pragma unroll
    for (int i = 0; i < 4; i++) {
        int f = tid + (i << 8);
        int row = f >> 3, c4 = (f & 7) << 2;
        cp16(As + SWZ32(row, c4), A + (size_t)(m0 + row) * GSTRIDE + kc + c4);
    }
#pragma unroll
    for (int i = 0; i < 8; i++) {
        int f = tid + (i << 8);
        int row = f >> 3, c4 = (f & 7) << 2;
        cp16(Bs + SWZ32(row, c4), W + (size_t)(n0 + row) * GSTRIDE + kc + c4);
    }
}

__device__ __forceinline__ void gemm_body(
    const uint32_t* __restrict__ A, const uint32_t* __restrict__ W,
    float* __restrict__ Cf, uint32_t* __restrict__ Ch, int mode, float scale)
{
    extern __shared__ uint32_t smg[];

    const int tid  = threadIdx.x;
    const int lane = tid & 31;
    const int wid  = tid >> 5;
    const int wm0  = (wid & 1) << 6;
    const int wn0  = (wid >> 1) << 6;
    const int m0   = blockIdx.y * BM;
    const int n0   = blockIdx.x * BN;
    const int r0   = lane >> 2;
    const int tig  = lane & 3;

    /* ldmatrix lane constants */
    const int lgrp = lane >> 3, lrow = lane & 7;
    const int a_roff = ((lgrp & 1) << 3) + lrow, a_coff = (lgrp >> 1) << 2;
    const int b_roff = ((lgrp >> 1) << 3) + lrow, b_coff = (lgrp & 1) << 2;

    const uint32_t sb = (uint32_t)__cvta_generic_to_shared(smg);

    float acc[4][8][4];
#pragma unroll
    for (int mt = 0; mt < 4; mt++)
#pragma unroll
        for (int nt = 0; nt < 8; nt++)
#pragma unroll
            for (int e = 0; e < 4; e++) acc[mt][nt][e] = 0.f;

#pragma unroll
    for (int p = 0; p < NSTAGE - 1; p++) {
        stage_async(smg + p * STG_U32, smg + p * STG_U32 + A_U32,
                    A, W, m0, n0, p * ROWU, tid);
        CP_COMMIT();
    }

    for (int kt = 0; kt < NKT; kt++) {
        CP_WAIT(NSTAGE - 2);
        __syncthreads();

        if (kt + NSTAGE - 1 < NKT) {
            const int w = (kt + NSTAGE - 1) % NSTAGE;
            stage_async(smg + w * STG_U32, smg + w * STG_U32 + A_U32,
                        A, W, m0, n0, (kt + NSTAGE - 1) * ROWU, tid);
        }
        CP_COMMIT();

        const uint32_t abase = sb + (uint32_t)((kt % NSTAGE) * STG_U32) * 4u;
        const uint32_t bbase = abase + A_U32 * 4u;
#pragma unroll
        for (int ks = 0; ks < 4; ks++) {
            const int c0 = ks << 3;
            uint32_t af[4][4], bf[8][2];
#pragma unroll
            for (int mt = 0; mt < 4; mt++) {
                int row = wm0 + (mt << 4) + a_roff;
                int col = c0 + a_coff;
                ldsm_x4(af[mt][0], af[mt][1], af[mt][2], af[mt][3],
                        abase + 4u * (uint32_t)SWZ32(row, col));
            }
#pragma unroll
            for (int p2 = 0; p2 < 4; p2++) {
                int n = wn0 + (p2 << 4) + b_roff;
                int col = c0 + b_coff;
                ldsm_x4(bf[2*p2][0], bf[2*p2][1], bf[2*p2+1][0], bf[2*p2+1][1],
                        bbase + 4u * (uint32_t)SWZ32(n, col));
            }
#pragma unroll
            for (int mt = 0; mt < 4; mt++)
#pragma unroll
                for (int nt = 0; nt < 8; nt++)
                    mma_f16(acc[mt][nt], af[mt], bf[nt]);
        }
    }

#pragma unroll
    for (int mt = 0; mt < 4; mt++) {
#pragma unroll
        for (int half = 0; half < 2; half++) {
            const int m = m0 + wm0 + (mt << 4) + r0 + (half << 3);
            if (mode == 1) {
                const int b = m >> 11, srow = m & (SEQ - 1);
#pragma unroll
                for (int nt = 0; nt < 8; nt++) {
                    int col = n0 + wn0 + (nt << 3) + (tig << 1);
                    int h = col >> 6, dd = col & 63;
                    uint32_t val = h2pack(acc[mt][nt][half * 2]     * scale,
                                          acc[mt][nt][half * 2 + 1] * scale);
                    Ch[((size_t)((b * NH + h) * SEQ + srow) << 5) + (dd >> 1)] = val;
                }
            } else {
#pragma unroll
                for (int nt = 0; nt < 8; nt++) {
                    int col = n0 + wn0 + (nt << 3) + (tig << 1);
                    float2 val = make_float2(acc[mt][nt][half * 2],
                                             acc[mt][nt][half * 2 + 1]);
                    *(float2*)(Cf + (size_t)m * DIM + col) = val;
                }
            }
        }
    }
}

__global__ __launch_bounds__(256) void gemm_qkv(
    const uint32_t* __restrict__ qt, const uint32_t* __restrict__ kt_,
    const uint32_t* __restrict__ vt, const uint32_t* __restrict__ wq,
    const uint32_t* __restrict__ wk, const uint32_t* __restrict__ wv,
    uint32_t* __restrict__ qh, uint32_t* __restrict__ kh, uint32_t* __restrict__ vh)
{
    const uint32_t* A; const uint32_t* W; uint32_t* C; float scale;
    if (blockIdx.z == 0)      { A = qt;  W = wq; C = qh; scale = 0.125f * 1.44269504f; }
    else if (blockIdx.z == 1) { A = kt_; W = wk; C = kh; scale = 1.0f; }
    else                      { A = vt;  W = wv; C = vh; scale = 1.0f; }
    gemm_body(A, W, nullptr, C, 1, scale);
}

__global__ __launch_bounds__(256) void gemm_out(
    const uint32_t* __restrict__ A, const uint32_t* __restrict__ W,
    float* __restrict__ C)
{
    gemm_body(A, W, C, nullptr, 0, 1.0f);
}

/* ============ fp16 tensor-core flash attention (causal) ===================
   Q frags in regs; K frags via ldmatrix.x4; V via ldmatrix.x4.trans;
   P packed in regs via f16x2 ex2; K,V double-buffered, 1 sync/tile.
   SMEM: Q 16K | K0 8K | K1 8K | V0 8K | V1 8K = 48 KB.                     */

__global__ __launch_bounds__(128) void flash_attn(
    const uint32_t* __restrict__ Qh, const uint32_t* __restrict__ Kh,
    const uint32_t* __restrict__ Vh, uint32_t* __restrict__ AO)
{
    extern __shared__ uint32_t fsm[];
    uint32_t* Qs     = fsm;                       /* 128 x 32 u32 */
    uint32_t* Ksb[2] = { fsm + 4096, fsm + 6144 };/* 64 x 32 each */
    uint32_t* Vsb[2] = { fsm + 8192, fsm + 10240 };

    const int bh = blockIdx.y;
    const int qt = gridDim.x - 1 - blockIdx.x;    /* heavy tiles first */
    const int q0 = qt * 128;
    const uint32_t* Qb = Qh + (size_t)bh * SEQ * (HD/2);
    const uint32_t* Kb = Kh + (size_t)bh * SEQ * (HD/2);
    const uint32_t* Vb = Vh + (size_t)bh * SEQ * (HD/2);

    const int tid  = threadIdx.x;
    const int lane = tid & 31;
    const int wid  = tid >> 5;
    const int r0   = lane >> 2;
    const int tig  = lane & 3;
    const int wq   = wid << 5;

    /* ldmatrix lane constants */
    const int lgrp = lane >> 3, lrow = lane & 7;
    const int b_roff = ((lgrp >> 1) << 3) + lrow, b_coff = (lgrp & 1) << 2;
    const int lm_key = ((lgrp & 1) << 3) + lrow;  /* for V trans */
    const int lm_nt2 = lgrp >> 1;

    /* group A: Q tile */
#pragma unroll
    for (int i = 0; i < 8; i++) {
        int f = tid + (i << 7);
        int row = f >> 3, c4 = (f & 7) << 2;
        cp16(Qs + SWZ32(row, c4), Qb + (size_t)(q0 + row) * (HD/2) + c4);
    }
    CP_COMMIT();
    /* group B: K[0] + V[0] */
#pragma unroll
    for (int i = 0; i < 4; i++) {
        int f = tid + (i << 7);
        int row = f >> 3, c4 = (f & 7) << 2;
        cp16(Ksb[0] + SWZ32(row, c4), Kb + (size_t)row * (HD/2) + c4);
    }
#pragma unroll
    for (int i = 0; i < 4; i++) {
        int f = tid + (i << 7);
        int row = f >> 3, c4 = (f & 7) << 2;
        cp16(Vsb[0] + SWZ32(row, c4), Vb + (size_t)row * (HD/2) + c4);
    }
    CP_COMMIT();

    CP_WAIT(1);
    __syncthreads();

    /* Q fragments to registers */
    uint32_t qf[4][2][4];
#pragma unroll
    for (int ks = 0; ks < 4; ks++) {
        const int kb = (ks << 3) + tig;
#pragma unroll
        for (int mt = 0; mt < 2; mt++) {
            int row = wq + (mt << 4) + r0;
            qf[ks][mt][0] = Qs[SWZ32(row,     kb)];
            qf[ks][mt][1] = Qs[SWZ32(row + 8, kb)];
            qf[ks][mt][2] = Qs[SWZ32(row,     kb + 4)];
            qf[ks][mt][3] = Qs[SWZ32(row + 8, kb + 4)];
        }
    }

    float o[2][8][4];
    float mi[4], li[4];
#pragma unroll
    for (int i = 0; i < 4; i++) { mi[i] = -1e30f; li[i] = 0.f; }
#pragma unroll
    for (int mt = 0; mt < 2; mt++)
#pragma unroll
        for (int nt = 0; nt < 8; nt++)
#pragma unroll
            for (int e = 0; e < 4; e++) o[mt][nt][e] = 0.f;

    const int nkt = 2 * qt + 2;
    for (int kt = 0; kt < nkt; kt++) {
        const int k0 = kt << 6;

        CP_WAIT(0);
        __syncthreads();

        if (kt + 1 < nkt) {
            const uint32_t* Kp = Kb + (size_t)(k0 + 64) * (HD/2);
            const uint32_t* Vp = Vb + (size_t)(k0 + 64) * (HD/2);
            uint32_t* Kd = Ksb[(kt + 1) & 1];
            uint32_t* Vd = Vsb[(kt + 1) & 1];
#pragma unroll
            for (int i = 0; i < 4; i++) {
                int f = tid + (i << 7);
                int row = f >> 3, c4 = (f & 7) << 2;
                cp16(Kd + SWZ32(row, c4), Kp + (size_t)row * (HD/2) + c4);
            }
#pragma unroll
            for (int i = 0; i < 4; i++) {
                int f = tid + (i << 7);
                int row = f >> 3, c4 = (f & 7) << 2;
                cp16(Vd + SWZ32(row, c4), Vp + (size_t)row * (HD/2) + c4);
            }
            CP_COMMIT();
        }

        const uint32_t kbase = (uint32_t)__cvta_generic_to_shared(Ksb[kt & 1]);
        const uint32_t vbase = (uint32_t)__cvta_generic_to_shared(Vsb[kt & 1]);
        const bool active = (k0 <= q0 + wq + 31);
        if (active) {
            /* S = Q K^T : A from regs, B via ldmatrix.x4 */
            float s[2][8][4];
#pragma unroll
            for (int mt = 0; mt < 2; mt++)
#pragma unroll
                for (int nt = 0; nt < 8; nt++)
#pragma unroll
                    for (int e = 0; e < 4; e++) s[mt][nt][e] = 0.f;

#pragma unroll
            for (int ks = 0; ks < 4; ks++) {
                const int c0 = ks << 3;
                uint32_t bf[8][2];
#pragma unroll
                for (int p2 = 0; p2 < 4; p2++) {
                    int n = (p2 << 4) + b_roff;
                    ldsm_x4(bf[2*p2][0], bf[2*p2][1], bf[2*p2+1][0], bf[2*p2+1][1],
                            kbase + 4u * (uint32_t)SWZ32(n, c0 + b_coff));
                }
#pragma unroll
                for (int mt = 0; mt < 2; mt++)
#pragma unroll
                    for (int nt = 0; nt < 8; nt++)
                        mma_f16(s[mt][nt], qf[ks][mt], bf[nt]);
            }

            /* causal mask near diagonal */
            if (k0 + 63 > q0 + wq) {
#pragma unroll
                for (int mt = 0; mt < 2; mt++)
#pragma unroll
                    for (int nt = 0; nt < 8; nt++)
#pragma unroll
                        for (int e = 0; e < 4; e++) {
                            int rg = q0 + wq + (mt << 4) + ((e >> 1) << 3) + r0;
                            int cg = k0 + (nt << 3) + (tig << 1) + (e & 1);
                            if (cg > rg) s[mt][nt][e] = -1e30f;
                        }
            }

            /* online softmax (base-2); P packed to f16x2 in regs */
            uint32_t pk[2][8][2];
#pragma unroll
            for (int mt = 0; mt < 2; mt++) {
#pragma unroll
                for (int half = 0; half < 2; half++) {
                    const int ri = mt * 2 + half;
                    float mx = -1e30f;
#pragma unroll
                    for (int nt = 0; nt < 8; nt++)
                        mx = fmaxf(mx, fmaxf(s[mt][nt][half*2], s[mt][nt][half*2+1]));
                    mx = fmaxf(mx, __shfl_xor_sync(0xffffffffu, mx, 1));
                    mx = fmaxf(mx, __shfl_xor_sync(0xffffffffu, mx, 2));
                    float mnew = fmaxf(mi[ri], mx);
                    float corr = ex2f(mi[ri] - mnew);
                    uint32_t sA = 0, sB = 0;   /* two hadd2 accumulators */
#pragma unroll
                    for (int nt = 0; nt < 8; nt++) {
                        float x0 = s[mt][nt][half*2]     - mnew;
                        float x1 = s[mt][nt][half*2 + 1] - mnew;
                        uint32_t pe = ex2_h2(cvt_f16x2(x1, x0));
                        pk[mt][nt][half] = pe;
                        if (nt & 1) sB = hadd2u(sB, pe); else sA = hadd2u(sA, pe);
                    }
                    float2 sf = __half22float2(*(__half2*)&(sA = hadd2u(sA, sB)));
                    float sum = sf.x + sf.y;
                    sum += __shfl_xor_sync(0xffffffffu, sum, 1);
                    sum += __shfl_xor_sync(0xffffffffu, sum, 2);
                    li[ri] = li[ri] * corr + sum;
                    mi[ri] = mnew;
#pragma unroll
                    for (int nt = 0; nt < 8; nt++) {
                        o[mt][nt][half*2]     *= corr;
                        o[mt][nt][half*2 + 1] *= corr;
                    }
                }
            }

            /* O += P V : A = pk (already packed), B via ldmatrix.trans */
#pragma unroll
            for (int ks = 0; ks < 4; ks++) {
                uint32_t bf[8][2];
#pragma unroll
                for (int j = 0; j < 4; j++) {
                    int key = (ks << 4) + lm_key;
                    int c   = ((j << 1) + lm_nt2) << 2;
                    uint32_t t0, t1, t2, t3;
                    asm volatile(
                        "ldmatrix.sync.aligned.m8n8.x4.trans.shared.b16 "
                        "{%0,%1,%2,%3}, [%4];"
                        : "=r"(t0), "=r"(t1), "=r"(t2), "=r"(t3)
                        : "r"(vbase + 4u * (uint32_t)SWZ32(key, c)));
                    bf[(j << 1)    ][0] = t0;
                    bf[(j << 1)    ][1] = t1;
                    bf[(j << 1) + 1][0] = t2;
                    bf[(j << 1) + 1][1] = t3;
                }
#pragma unroll
                for (int mt = 0; mt < 2; mt++) {
                    uint32_t af[4] = { pk[mt][2*ks][0], pk[mt][2*ks][1],
                                       pk[mt][2*ks+1][0], pk[mt][2*ks+1][1] };
#pragma unroll
                    for (int nt = 0; nt < 8; nt++)
                        mma_f16(o[mt][nt], af, bf[nt]);
                }
            }
        }
    }

    /* epilogue: normalize, store packed fp16 into AO */
    const int b = bh >> 4, h = bh & 15;
#pragma unroll
    for (int mt = 0; mt < 2; mt++) {
#pragma unroll
        for (int half = 0; half < 2; half++) {
            const float inv = 1.f / li[mt * 2 + half];
            const int rg = q0 + wq + (mt << 4) + (half << 3) + r0;
            uint32_t* row = AO + (size_t)(b * SEQ + rg) * GSTRIDE + (h << 5);
#pragma unroll
            for (int nt = 0; nt < 8; nt++) {
                row[(nt << 2) + tig] = h2pack(o[mt][nt][half*2]     * inv,
                                              o[mt][nt][half*2 + 1] * inv);
            }
        }
    }
}

/* ---------------- launch -------------------------------------------------- */
extern "C" void kernel_launch(void* const* d_in, const int* in_sizes, int n_in,
                              void* d_out, int out_size)
{
    const float* q  = (const float*)d_in[0];
    const float* k  = (const float*)d_in[1];
    const float* v  = (const float*)d_in[2];
    const float* wq = (const float*)d_in[3];
    const float* wk = (const float*)d_in[4];
    const float* wv = (const float*)d_in[5];
    const float* wo = (const float*)d_in[6];

    uint32_t *qt, *kt, *vt, *wqt, *wkt, *wvt, *wot, *qh, *kh, *vh, *ao;
    cudaGetSymbolAddress((void**)&qt,  g_qt);
    cudaGetSymbolAddress((void**)&kt,  g_kt);
    cudaGetSymbolAddress((void**)&vt,  g_vt);
    cudaGetSymbolAddress((void**)&wqt, g_wq);
    cudaGetSymbolAddress((void**)&wkt, g_wk);
    cudaGetSymbolAddress((void**)&wvt, g_wv);
    cudaGetSymbolAddress((void**)&wot, g_wo);
    cudaGetSymbolAddress((void**)&qh,  g_qh);
    cudaGetSymbolAddress((void**)&kh,  g_kh);
    cudaGetSymbolAddress((void**)&vh,  g_vh);
    cudaGetSymbolAddress((void**)&ao,  g_ao);

    const int flash_smem = 12288 * 4;   /* 49152 */
    cudaFuncSetAttribute(gemm_qkv,  cudaFuncAttributeMaxDynamicSharedMemorySize, GEMM_SMEM);
    cudaFuncSetAttribute(gemm_out,  cudaFuncAttributeMaxDynamicSharedMemorySize, GEMM_SMEM);
    cudaFuncSetAttribute(flash_attn, cudaFuncAttributeMaxDynamicSharedMemorySize, flash_smem);

    dim3 gcvt(MROWS * DIM / 4 / 256, 7);     /* 4096 x 7 */
    cvt_all_kernel<<<gcvt, 256>>>(q, k, v, wq, wk, wv, wo,
                                  qt, kt, vt, wqt, wkt, wvt, wot);

    dim3 gqkv(DIM / BN, MROWS / BM, 3);        /* 4 x 32 x 3 */
    gemm_qkv<<<gqkv, 256, GEMM_SMEM>>>(qt, kt, vt, wqt, wkt, wvt, qh, kh, vh);

    flash_attn<<<dim3(SEQ / 128, BATCH * NH), 128, flash_smem>>>(qh, kh, vh, ao);

    dim3 gout(DIM / BN, MROWS / BM);           /* 4 x 32 */
    gemm_out<<<gout, 256, GEMM_SMEM>>>(ao, wot, (float*)d_out);
}

// round 11
// speedup vs baseline: 2.0434x; 1.0356x over previous
#include <cuda_runtime.h>
#include <cuda_fp16.h>
#include <cstdint>

#define DIM   1024
#define SEQ   2048
#define BATCH 2
#define NH    16
#define HD    64
#define MROWS (BATCH*SEQ)   /* 4096 */

/* ------------- scratch (device globals, fp16 packed as u32) -------------- */
__device__ uint32_t g_qt[MROWS*DIM/2];
__device__ uint32_t g_kt[MROWS*DIM/2];
__device__ uint32_t g_vt[MROWS*DIM/2];
__device__ uint32_t g_wq[DIM*DIM/2];
__device__ uint32_t g_wk[DIM*DIM/2];
__device__ uint32_t g_wv[DIM*DIM/2];
__device__ uint32_t g_wo[DIM*DIM/2];
__device__ uint32_t g_qh[BATCH*NH*SEQ*HD/2];  /* [B,H,S,hd/2], Q pre-scaled */
__device__ uint32_t g_kh[BATCH*NH*SEQ*HD/2];
__device__ uint32_t g_vh[BATCH*NH*SEQ*HD/2];
__device__ uint32_t g_ao[MROWS*DIM/2];        /* [B*S, D/2] attn output */

__device__ __forceinline__ uint32_t h2pack(float lo, float hi) {
    __half2 h = __floats2half2_rn(lo, hi);
    return *(uint32_t*)&h;
}
__device__ __forceinline__ float ex2f(float x) {
    float r;
    asm("ex2.approx.ftz.f32 %0, %1;" : "=f"(r) : "f"(x));
    return r;
}
__device__ __forceinline__ uint32_t cvt_f16x2(float hi, float lo) {
    uint32_t r;
    asm("cvt.rn.f16x2.f32 %0, %1, %2;" : "=r"(r) : "f"(hi), "f"(lo));
    return r;
}
__device__ __forceinline__ uint32_t ex2_h2(uint32_t x) {
    uint32_t r;
    asm("ex2.approx.f16x2 %0, %1;" : "=r"(r) : "r"(x));
    return r;
}
__device__ __forceinline__ uint32_t hadd2u(uint32_t a, uint32_t b) {
    uint32_t r;
    asm("add.rn.f16x2 %0, %1, %2;" : "=r"(r) : "r"(a), "r"(b));
    return r;
}

__device__ __forceinline__ void mma_f16(float* d, const uint32_t* a, const uint32_t* b) {
    asm volatile(
        "mma.sync.aligned.m16n8k16.row.col.f32.f16.f16.f32 "
        "{%0,%1,%2,%3}, {%4,%5,%6,%7}, {%8,%9}, {%0,%1,%2,%3};\n"
        : "+f"(d[0]), "+f"(d[1]), "+f"(d[2]), "+f"(d[3])
        : "r"(a[0]), "r"(a[1]), "r"(a[2]), "r"(a[3]), "r"(b[0]), "r"(b[1]));
}

__device__ __forceinline__ void ldsm_x4(uint32_t& r0, uint32_t& r1,
                                        uint32_t& r2, uint32_t& r3, uint32_t addr) {
    asm volatile("ldmatrix.sync.aligned.m8n8.x4.shared.b16 {%0,%1,%2,%3}, [%4];"
                 : "=r"(r0), "=r"(r1), "=r"(r2), "=r"(r3) : "r"(addr));
}

__device__ __forceinline__ void cp16(uint32_t* smem_dst, const uint32_t* gsrc) {
    uint32_t sa = (uint32_t)__cvta_generic_to_shared(smem_dst);
    asm volatile("cp.async.cg.shared.global [%0], [%1], 16;"
                 :: "r"(sa), "l"(gsrc) : "memory");
}
#define CP_COMMIT() asm volatile("cp.async.commit_group;" ::: "memory")
#define CP_WAIT(n)  asm volatile("cp.async.wait_group %0;" :: "n"(n) : "memory")

/* xor swizzle for 32-u32 (64-half) rows: 16B-aligned, conflict-free        */
#define SWZ32(row, c) ((row) * 32 + ((c) ^ (((row) & 7) << 2)))

/* ------------------- fused fp32 -> fp16 convert --------------------------- */
__global__ __launch_bounds__(256) void cvt_all_kernel(
    const float* __restrict__ s0, const float* __restrict__ s1,
    const float* __restrict__ s2, const float* __restrict__ s3,
    const float* __restrict__ s4, const float* __restrict__ s5,
    const float* __restrict__ s6,
    uint32_t* __restrict__ d0, uint32_t* __restrict__ d1,
    uint32_t* __restrict__ d2, uint32_t* __restrict__ d3,
    uint32_t* __restrict__ d4, uint32_t* __restrict__ d5,
    uint32_t* __restrict__ d6)
{
    const float* srcs[7] = { s0, s1, s2, s3, s4, s5, s6 };
    uint32_t*    dsts[7] = { d0, d1, d2, d3, d4, d5, d6 };
    const int ns[7] = { MROWS*DIM/4, MROWS*DIM/4, MROWS*DIM/4,
                        DIM*DIM/4, DIM*DIM/4, DIM*DIM/4, DIM*DIM/4 };
    const int t = blockIdx.y;
    const int i = blockIdx.x * 256 + threadIdx.x;
    if (i < ns[t]) {
        float4 v = *(const float4*)(srcs[t] + (size_t)i * 4);
        uint2 o = make_uint2(h2pack(v.x, v.y), h2pack(v.z, v.w));
        *(uint2*)(dsts[t] + (size_t)i * 2) = o;
    }
}

/* =================== fp16 GEMM: C = A @ W^T ===============================
   block 128x128, 256 thr / 8 warps (2x4), warp tile 64x32, NSTAGE=3,
   96 KB SMEM -> 2 CTAs/SM (16 warps/SM).                                   */
#define BM 128
#define BN 128
#define NKT 16                      /* 16 k-tiles of 64 halves */
#define ROWU 32                     /* u32 per tile row */
#define A_U32 (BM * ROWU)           /* 4096  */
#define B_U32 (BN * ROWU)           /* 4096  */
#define STG_U32 (A_U32 + B_U32)     /* 8192  */
#define NSTAGE 3
#define GEMM_SMEM (NSTAGE * STG_U32 * 4)  /* 98304 B */
#define GSTRIDE (DIM / 2)           /* 512 u32 per gmem row */

__device__ __forceinline__ void stage_async(
    uint32_t* __restrict__ As, uint32_t* __restrict__ Bs,
    const uint32_t* __restrict__ A, const uint32_t* __restrict__ W,
    int m0, int n0, int kc, int tid)
{
#pragma unroll
    for (int i = 0; i < 4; i++) {
        int f = tid + (i << 8);
        int row = f >> 3, c4 = (f & 7) << 2;
        cp16(As + SWZ32(row, c4), A + (size_t)(m0 + row) * GSTRIDE + kc + c4);
    }
#pragma unroll
    for (int i = 0; i < 4; i++) {
        int f = tid + (i << 8);
        int row = f >> 3, c4 = (f & 7) << 2;
        cp16(Bs + SWZ32(row, c4), W + (size_t)(n0 + row) * GSTRIDE + kc + c4);
    }
}

__device__ __forceinline__ void gemm_body(
    const uint32_t* __restrict__ A, const uint32_t* __restrict__ W,
    float* __restrict__ Cf, uint32_t* __restrict__ Ch, int mode, float scale)
{
    extern __shared__ uint32_t smg[];

    const int tid  = threadIdx.x;
    const int lane = tid & 31;
    const int wid  = tid >> 5;
    const int wm0  = (wid >> 2) << 6;       /* 0 or 64         */
    const int wn0  = (wid & 3) << 5;        /* 0,32,64,96      */
    const int m0   = blockIdx.y * BM;
    const int n0   = blockIdx.x * BN;
    const int r0   = lane >> 2;
    const int tig  = lane & 3;

    /* ldmatrix lane constants */
    const int lgrp = lane >> 3, lrow = lane & 7;
    const int a_roff = ((lgrp & 1) << 3) + lrow, a_coff = (lgrp >> 1) << 2;
    const int b_roff = ((lgrp >> 1) << 3) + lrow, b_coff = (lgrp & 1) << 2;

    const uint32_t sb = (uint32_t)__cvta_generic_to_shared(smg);

    float acc[4][4][4];
#pragma unroll
    for (int mt = 0; mt < 4; mt++)
#pragma unroll
        for (int nt = 0; nt < 4; nt++)
#pragma unroll
            for (int e = 0; e < 4; e++) acc[mt][nt][e] = 0.f;

#pragma unroll
    for (int p = 0; p < NSTAGE - 1; p++) {
        stage_async(smg + p * STG_U32, smg + p * STG_U32 + A_U32,
                    A, W, m0, n0, p * ROWU, tid);
        CP_COMMIT();
    }

    for (int kt = 0; kt < NKT; kt++) {
        CP_WAIT(NSTAGE - 2);
        __syncthreads();

        if (kt + NSTAGE - 1 < NKT) {
            const int w = (kt + NSTAGE - 1) % NSTAGE;
            stage_async(smg + w * STG_U32, smg + w * STG_U32 + A_U32,
                        A, W, m0, n0, (kt + NSTAGE - 1) * ROWU, tid);
        }
        CP_COMMIT();

        const uint32_t abase = sb + (uint32_t)((kt % NSTAGE) * STG_U32) * 4u;
        const uint32_t bbase = abase + A_U32 * 4u;
#pragma unroll
        for (int ks = 0; ks < 4; ks++) {
            const int c0 = ks << 3;
            uint32_t af[4][4], bf[4][2];
#pragma unroll
            for (int mt = 0; mt < 4; mt++) {
                int row = wm0 + (mt << 4) + a_roff;
                ldsm_x4(af[mt][0], af[mt][1], af[mt][2], af[mt][3],
                        abase + 4u * (uint32_t)SWZ32(row, c0 + a_coff));
            }
#pragma unroll
            for (int p2 = 0; p2 < 2; p2++) {
                int n = wn0 + (p2 << 4) + b_roff;
                ldsm_x4(bf[2*p2][0], bf[2*p2][1], bf[2*p2+1][0], bf[2*p2+1][1],
                        bbase + 4u * (uint32_t)SWZ32(n, c0 + b_coff));
            }
#pragma unroll
            for (int mt = 0; mt < 4; mt++)
#pragma unroll
                for (int nt = 0; nt < 4; nt++)
                    mma_f16(acc[mt][nt], af[mt], bf[nt]);
        }
    }

#pragma unroll
    for (int mt = 0; mt < 4; mt++) {
#pragma unroll
        for (int half = 0; half < 2; half++) {
            const int m = m0 + wm0 + (mt << 4) + r0 + (half << 3);
            if (mode == 1) {
                const int b = m >> 11, srow = m & (SEQ - 1);
#pragma unroll
                for (int nt = 0; nt < 4; nt++) {
                    int col = n0 + wn0 + (nt << 3) + (tig << 1);
                    int h = col >> 6, dd = col & 63;
                    uint32_t val = h2pack(acc[mt][nt][half * 2]     * scale,
                                          acc[mt][nt][half * 2 + 1] * scale);
                    Ch[((size_t)((b * NH + h) * SEQ + srow) << 5) + (dd >> 1)] = val;
                }
            } else {
#pragma unroll
                for (int nt = 0; nt < 4; nt++) {
                    int col = n0 + wn0 + (nt << 3) + (tig << 1);
                    float2 val = make_float2(acc[mt][nt][half * 2],
                                             acc[mt][nt][half * 2 + 1]);
                    *(float2*)(Cf + (size_t)m * DIM + col) = val;
                }
            }
        }
    }
}

__global__ __launch_bounds__(256, 2) void gemm_qkv(
    const uint32_t* __restrict__ qt, const uint32_t* __restrict__ kt_,
    const uint32_t* __restrict__ vt, const uint32_t* __restrict__ wq,
    const uint32_t* __restrict__ wk, const uint32_t* __restrict__ wv,
    uint32_t* __restrict__ qh, uint32_t* __restrict__ kh, uint32_t* __restrict__ vh)
{
    const uint32_t* A; const uint32_t* W; uint32_t* C; float scale;
    if (blockIdx.z == 0)      { A = qt;  W = wq; C = qh; scale = 0.125f * 1.44269504f; }
    else if (blockIdx.z == 1) { A = kt_; W = wk; C = kh; scale = 1.0f; }
    else                      { A = vt;  W = wv; C = vh; scale = 1.0f; }
    gemm_body(A, W, nullptr, C, 1, scale);
}

__global__ __launch_bounds__(256, 2) void gemm_out(
    const uint32_t* __restrict__ A, const uint32_t* __restrict__ W,
    float* __restrict__ C)
{
    gemm_body(A, W, C, nullptr, 0, 1.0f);
}

/* ============ fp16 tensor-core flash attention (causal) ===================
   (unchanged from R10 — frozen this round)                                  */

__global__ __launch_bounds__(128) void flash_attn(
    const uint32_t* __restrict__ Qh, const uint32_t* __restrict__ Kh,
    const uint32_t* __restrict__ Vh, uint32_t* __restrict__ AO)
{
    extern __shared__ uint32_t fsm[];
    uint32_t* Qs     = fsm;                       /* 128 x 32 u32 */
    uint32_t* Ksb[2] = { fsm + 4096, fsm + 6144 };
    uint32_t* Vsb[2] = { fsm + 8192, fsm + 10240 };

    const int bh = blockIdx.y;
    const int qt = gridDim.x - 1 - blockIdx.x;
    const int q0 = qt * 128;
    const uint32_t* Qb = Qh + (size_t)bh * SEQ * (HD/2);
    const uint32_t* Kb = Kh + (size_t)bh * SEQ * (HD/2);
    const uint32_t* Vb = Vh + (size_t)bh * SEQ * (HD/2);

    const int tid  = threadIdx.x;
    const int lane = tid & 31;
    const int wid  = tid >> 5;
    const int r0   = lane >> 2;
    const int tig  = lane & 3;
    const int wq   = wid << 5;

    const int lgrp = lane >> 3, lrow = lane & 7;
    const int b_roff = ((lgrp >> 1) << 3) + lrow, b_coff = (lgrp & 1) << 2;
    const int lm_key = ((lgrp & 1) << 3) + lrow;
    const int lm_nt2 = lgrp >> 1;

#pragma unroll
    for (int i = 0; i < 8; i++) {
        int f = tid + (i << 7);
        int row = f >> 3, c4 = (f & 7) << 2;
        cp16(Qs + SWZ32(row, c4), Qb + (size_t)(q0 + row) * (HD/2) + c4);
    }
    CP_COMMIT();
#pragma unroll
    for (int i = 0; i < 4; i++) {
        int f = tid + (i << 7);
        int row = f >> 3, c4 = (f & 7) << 2;
        cp16(Ksb[0] + SWZ32(row, c4), Kb + (size_t)row * (HD/2) + c4);
    }
#pragma unroll
    for (int i = 0; i < 4; i++) {
        int f = tid + (i << 7);
        int row = f >> 3, c4 = (f & 7) << 2;
        cp16(Vsb[0] + SWZ32(row, c4), Vb + (size_t)row * (HD/2) + c4);
    }
    CP_COMMIT();

    CP_WAIT(1);
    __syncthreads();

    uint32_t qf[4][2][4];
#pragma unroll
    for (int ks = 0; ks < 4; ks++) {
        const int kb = (ks << 3) + tig;
#pragma unroll
        for (int mt = 0; mt < 2; mt++) {
            int row = wq + (mt << 4) + r0;
            qf[ks][mt][0] = Qs[SWZ32(row,     kb)];
            qf[ks][mt][1] = Qs[SWZ32(row + 8, kb)];
            qf[ks][mt][2] = Qs[SWZ32(row,     kb + 4)];
            qf[ks][mt][3] = Qs[SWZ32(row + 8, kb + 4)];
        }
    }

    float o[2][8][4];
    float mi[4], li[4];
#pragma unroll
    for (int i = 0; i < 4; i++) { mi[i] = -1e30f; li[i] = 0.f; }
#pragma unroll
    for (int mt = 0; mt < 2; mt++)
#pragma unroll
        for (int nt = 0; nt < 8; nt++)
#pragma unroll
            for (int e = 0; e < 4; e++) o[mt][nt][e] = 0.f;

    const int nkt = 2 * qt + 2;
    for (int kt = 0; kt < nkt; kt++) {
        const int k0 = kt << 6;

        CP_WAIT(0);
        __syncthreads();

        if (kt + 1 < nkt) {
            const uint32_t* Kp = Kb + (size_t)(k0 + 64) * (HD/2);
            const uint32_t* Vp = Vb + (size_t)(k0 + 64) * (HD/2);
            uint32_t* Kd = Ksb[(kt + 1) & 1];
            uint32_t* Vd = Vsb[(kt + 1) & 1];
#pragma unroll
            for (int i = 0; i < 4; i++) {
                int f = tid + (i << 7);
                int row = f >> 3, c4 = (f & 7) << 2;
                cp16(Kd + SWZ32(row, c4), Kp + (size_t)row * (HD/2) + c4);
            }
#pragma unroll
            for (int i = 0; i < 4; i++) {
                int f = tid + (i << 7);
                int row = f >> 3, c4 = (f & 7) << 2;
                cp16(Vd + SWZ32(row, c4), Vp + (size_t)row * (HD/2) + c4);
            }
            CP_COMMIT();
        }

        const uint32_t kbase = (uint32_t)__cvta_generic_to_shared(Ksb[kt & 1]);
        const uint32_t vbase = (uint32_t)__cvta_generic_to_shared(Vsb[kt & 1]);
        const bool active = (k0 <= q0 + wq + 31);
        if (active) {
            float s[2][8][4];
#pragma unroll
            for (int mt = 0; mt < 2; mt++)
#pragma unroll
                for (int nt = 0; nt < 8; nt++)
#pragma unroll
                    for (int e = 0; e < 4; e++) s[mt][nt][e] = 0.f;

#pragma unroll
            for (int ks = 0; ks < 4; ks++) {
                const int c0 = ks << 3;
                uint32_t bf[8][2];
#pragma unroll
                for (int p2 = 0; p2 < 4; p2++) {
                    int n = (p2 << 4) + b_roff;
                    ldsm_x4(bf[2*p2][0], bf[2*p2][1], bf[2*p2+1][0], bf[2*p2+1][1],
                            kbase + 4u * (uint32_t)SWZ32(n, c0 + b_coff));
                }
#pragma unroll
                for (int mt = 0; mt < 2; mt++)
#pragma unroll
                    for (int nt = 0; nt < 8; nt++)
                        mma_f16(s[mt][nt], qf[ks][mt], bf[nt]);
            }

            if (k0 + 63 > q0 + wq) {
#pragma unroll
                for (int mt = 0; mt < 2; mt++)
#pragma unroll
                    for (int nt = 0; nt < 8; nt++)
#pragma unroll
                        for (int e = 0; e < 4; e++) {
                            int rg = q0 + wq + (mt << 4) + ((e >> 1) << 3) + r0;
                            int cg = k0 + (nt << 3) + (tig << 1) + (e & 1);
                            if (cg > rg) s[mt][nt][e] = -1e30f;
                        }
            }

            uint32_t pk[2][8][2];
#pragma unroll
            for (int mt = 0; mt < 2; mt++) {
#pragma unroll
                for (int half = 0; half < 2; half++) {
                    const int ri = mt * 2 + half;
                    float mx = -1e30f;
#pragma unroll
                    for (int nt = 0; nt < 8; nt++)
                        mx = fmaxf(mx, fmaxf(s[mt][nt][half*2], s[mt][nt][half*2+1]));
                    mx = fmaxf(mx, __shfl_xor_sync(0xffffffffu, mx, 1));
                    mx = fmaxf(mx, __shfl_xor_sync(0xffffffffu, mx, 2));
                    float mnew = fmaxf(mi[ri], mx);
                    float corr = ex2f(mi[ri] - mnew);
                    uint32_t sA = 0, sB = 0;
#pragma unroll
                    for (int nt = 0; nt < 8; nt++) {
                        float x0 = s[mt][nt][half*2]     - mnew;
                        float x1 = s[mt][nt][half*2 + 1] - mnew;
                        uint32_t pe = ex2_h2(cvt_f16x2(x1, x0));
                        pk[mt][nt][half] = pe;
                        if (nt & 1) sB = hadd2u(sB, pe); else sA = hadd2u(sA, pe);
                    }
                    float2 sf = __half22float2(*(__half2*)&(sA = hadd2u(sA, sB)));
                    float sum = sf.x + sf.y;
                    sum += __shfl_xor_sync(0xffffffffu, sum, 1);
                    sum += __shfl_xor_sync(0xffffffffu, sum, 2);
                    li[ri] = li[ri] * corr + sum;
                    mi[ri] = mnew;
#pragma unroll
                    for (int nt = 0; nt < 8; nt++) {
                        o[mt][nt][half*2]     *= corr;
                        o[mt][nt][half*2 + 1] *= corr;
                    }
                }
            }

#pragma unroll
            for (int ks = 0; ks < 4; ks++) {
                uint32_t bf[8][2];
#pragma unroll
                for (int j = 0; j < 4; j++) {
                    int key = (ks << 4) + lm_key;
                    int c   = ((j << 1) + lm_nt2) << 2;
                    uint32_t t0, t1, t2, t3;
                    asm volatile(
                        "ldmatrix.sync.aligned.m8n8.x4.trans.shared.b16 "
                        "{%0,%1,%2,%3}, [%4];"
                        : "=r"(t0), "=r"(t1), "=r"(t2), "=r"(t3)
                        : "r"(vbase + 4u * (uint32_t)SWZ32(key, c)));
                    bf[(j << 1)    ][0] = t0;
                    bf[(j << 1)    ][1] = t1;
                    bf[(j << 1) + 1][0] = t2;
                    bf[(j << 1) + 1][1] = t3;
                }
#pragma unroll
                for (int mt = 0; mt < 2; mt++) {
                    uint32_t af[4] = { pk[mt][2*ks][0], pk[mt][2*ks][1],
                                       pk[mt][2*ks+1][0], pk[mt][2*ks+1][1] };
#pragma unroll
                    for (int nt = 0; nt < 8; nt++)
                        mma_f16(o[mt][nt], af, bf[nt]);
                }
            }
        }
    }

    const int b = bh >> 4, h = bh & 15;
#pragma unroll
    for (int mt = 0; mt < 2; mt++) {
#pragma unroll
        for (int half = 0; half < 2; half++) {
            const float inv = 1.f / li[mt * 2 + half];
            const int rg = q0 + wq + (mt << 4) + (half << 3) + r0;
            uint32_t* row = AO + (size_t)(b * SEQ + rg) * GSTRIDE + (h << 5);
#pragma unroll
            for (int nt = 0; nt < 8; nt++) {
                row[(nt << 2) + tig] = h2pack(o[mt][nt][half*2]     * inv,
                                              o[mt][nt][half*2 + 1] * inv);
            }
        }
    }
}

/* ---------------- launch -------------------------------------------------- */
extern "C" void kernel_launch(void* const* d_in, const int* in_sizes, int n_in,
                              void* d_out, int out_size)
{
    const float* q  = (const float*)d_in[0];
    const float* k  = (const float*)d_in[1];
    const float* v  = (const float*)d_in[2];
    const float* wq = (const float*)d_in[3];
    const float* wk = (const float*)d_in[4];
    const float* wv = (const float*)d_in[5];
    const float* wo = (const float*)d_in[6];

    uint32_t *qt, *kt, *vt, *wqt, *wkt, *wvt, *wot, *qh, *kh, *vh, *ao;
    cudaGetSymbolAddress((void**)&qt,  g_qt);
    cudaGetSymbolAddress((void**)&kt,  g_kt);
    cudaGetSymbolAddress((void**)&vt,  g_vt);
    cudaGetSymbolAddress((void**)&wqt, g_wq);
    cudaGetSymbolAddress((void**)&wkt, g_wk);
    cudaGetSymbolAddress((void**)&wvt, g_wv);
    cudaGetSymbolAddress((void**)&wot, g_wo);
    cudaGetSymbolAddress((void**)&qh,  g_qh);
    cudaGetSymbolAddress((void**)&kh,  g_kh);
    cudaGetSymbolAddress((void**)&vh,  g_vh);
    cudaGetSymbolAddress((void**)&ao,  g_ao);

    const int flash_smem = 12288 * 4;   /* 49152 */
    cudaFuncSetAttribute(gemm_qkv,  cudaFuncAttributeMaxDynamicSharedMemorySize, GEMM_SMEM);
    cudaFuncSetAttribute(gemm_out,  cudaFuncAttributeMaxDynamicSharedMemorySize, GEMM_SMEM);
    cudaFuncSetAttribute(flash_attn, cudaFuncAttributeMaxDynamicSharedMemorySize, flash_smem);

    dim3 gcvt(MROWS * DIM / 4 / 256, 7);     /* 4096 x 7 */
    cvt_all_kernel<<<gcvt, 256>>>(q, k, v, wq, wk, wv, wo,
                                  qt, kt, vt, wqt, wkt, wvt, wot);

    dim3 gqkv(DIM / BN, MROWS / BM, 3);        /* 8 x 32 x 3 */
    gemm_qkv<<<gqkv, 256, GEMM_SMEM>>>(qt, kt, vt, wqt, wkt, wvt, qh, kh, vh);

    flash_attn<<<dim3(SEQ / 128, BATCH * NH), 128, flash_smem>>>(qh, kh, vh, ao);

    dim3 gout(DIM / BN, MROWS / BM);           /* 8 x 32 */
    gemm_out<<<gout, 256, GEMM_SMEM>>>(ao, wot, (float*)d_out);
}